// round 11
// baseline (speedup 1.0000x reference)
#include <cuda_runtime.h>
#include <cuda_bf16.h>
#include <cstdint>
#include <math.h>

// Problem constants (fixed by the dataset)
constexpr int cV = 50000;   // vocab
constexpr int cVp = 50048;  // vocab padded to 391*128
constexpr int cD = 256;     // embedding dim
constexpr int cH = 256;     // GRU hidden
constexpr int cB = 16;      // batch
constexpr int cT = 8;       // num_subtrees (time steps)
constexpr int cL = 512;     // subtree_len (nodes per graph)
constexpr int cE = 2048;    // edges per graph
constexpr int cG = cB * cT; // graphs = 128

// ------------------------- device scratch -------------------------
__device__ float g_embL[(size_t)cV * cD];   // emb_table @ Wl + bl
__device__ float g_embR[(size_t)cV * cD];   // emb_table @ Wr + br
__device__ __nv_bfloat16 g_Ahi[(size_t)cVp * cD];
__device__ __nv_bfloat16 g_Alo[(size_t)cVp * cD];
__device__ __nv_bfloat16 g_Bhi[2][cD * cD];  // W^T split hi: [z][n][k]
__device__ __nv_bfloat16 g_Blo[2][cD * cD];
__device__ int   g_tok[cG * cL];
__device__ float g_w[cG * cE];
__device__ float g_beta[cG];
__device__ float g_pooled[cG * cD];
__device__ float g_gi[2][cT * cB * 3 * cH];
__device__ float g_h[2][2][cB * cH];        // [dir][parity][b*H]
__device__ float g_ys[2][cT * cB * cH];
__device__ unsigned g_grubar[2];            // GRU inter-CTA barrier tickets

// ------------------------- small utils -------------------------
__device__ __forceinline__ float warp_sum(float v) {
    #pragma unroll
    for (int o = 16; o > 0; o >>= 1) v += __shfl_xor_sync(0xffffffffu, v, o);
    return v;
}
__device__ __forceinline__ void warp_sum2(float& v0, float& v1) {
    #pragma unroll
    for (int o = 16; o > 0; o >>= 1) {
        v0 += __shfl_xor_sync(0xffffffffu, v0, o);
        v1 += __shfl_xor_sync(0xffffffffu, v1, o);
    }
}
__device__ __forceinline__ void atomicMaxF(float* addr, float val) {
    int* ia = (int*)addr;
    int old = __float_as_int(*addr);
    while (__int_as_float(old) < val) {
        int prev = atomicCAS(ia, old, __float_as_int(val));
        if (prev == old) break;
        old = prev;
    }
}
__device__ __forceinline__ float sigmoidf_(float x) { return 1.0f / (1.0f + expf(-x)); }

// ------------------------- mma.sync helpers -------------------------
__device__ __forceinline__ uint32_t smem_u32(const void* p) {
    uint32_t a;
    asm("{ .reg .u64 t; cvta.to.shared.u64 t, %1; cvt.u32.u64 %0, t; }"
        : "=r"(a) : "l"(p));
    return a;
}
__device__ __forceinline__ void ldm_x4(uint32_t& r0, uint32_t& r1, uint32_t& r2,
                                       uint32_t& r3, uint32_t addr) {
    asm volatile("ldmatrix.sync.aligned.m8n8.x4.shared.b16 {%0,%1,%2,%3}, [%4];"
                 : "=r"(r0), "=r"(r1), "=r"(r2), "=r"(r3) : "r"(addr));
}
__device__ __forceinline__ void mma16816(float* d, uint32_t a0, uint32_t a1,
                                         uint32_t a2, uint32_t a3,
                                         uint32_t b0, uint32_t b1) {
    asm volatile(
        "mma.sync.aligned.m16n8k16.row.col.f32.bf16.bf16.f32 "
        "{%0,%1,%2,%3}, {%4,%5,%6,%7}, {%8,%9}, {%0,%1,%2,%3};"
        : "+f"(d[0]), "+f"(d[1]), "+f"(d[2]), "+f"(d[3])
        : "r"(a0), "r"(a1), "r"(a2), "r"(a3), "r"(b0), "r"(b1));
}
__device__ __forceinline__ void cpa16(uint32_t dst, const void* src) {
    asm volatile("cp.async.cg.shared.global [%0], [%1], 16;" :: "r"(dst),
                 "l"(src));
}
__device__ __forceinline__ void cpa_commit() {
    asm volatile("cp.async.commit_group;" ::: "memory");
}
template <int N>
__device__ __forceinline__ void cpa_wait() {
    asm volatile("cp.async.wait_group %0;" :: "n"(N) : "memory");
}

// ------------------------- K0: token LUT -------------------------
__global__ void k_tok(const int* __restrict__ token_ids) {
    int g = blockIdx.x, l = threadIdx.x;
    int b = g / cT, t = g % cT;
    g_tok[g * cL + l] = token_ids[(t * cL + l) * cB + b];
}

__global__ void k_zero() {
    int idx = blockIdx.x * 256 + threadIdx.x;
    ((float*)g_h)[idx] = 0.0f;
}

// ------------------------- split-precision conversion -------------------------
__global__ void __launch_bounds__(256) k_splitA(const float* __restrict__ emb) {
    size_t idx = ((size_t)blockIdx.x * 256 + threadIdx.x) * 8;
    int row = (int)(idx >> 8);
    float v[8];
    if (row < cV) {
        float4 a = *(const float4*)(emb + idx);
        float4 b = *(const float4*)(emb + idx + 4);
        v[0] = a.x; v[1] = a.y; v[2] = a.z; v[3] = a.w;
        v[4] = b.x; v[5] = b.y; v[6] = b.z; v[7] = b.w;
    } else {
        #pragma unroll
        for (int i = 0; i < 8; i++) v[i] = 0.0f;
    }
    __nv_bfloat16 hi[8], lo[8];
    #pragma unroll
    for (int i = 0; i < 8; i++) {
        hi[i] = __float2bfloat16_rn(v[i]);
        lo[i] = __float2bfloat16_rn(v[i] - __bfloat162float(hi[i]));
    }
    *(uint4*)(g_Ahi + idx) = *(uint4*)hi;
    *(uint4*)(g_Alo + idx) = *(uint4*)lo;
}

// W -> W^T hi/lo bf16 (B operand is [n][k], K-contiguous)
__global__ void __launch_bounds__(256) k_splitB(const float* __restrict__ Wl,
                                                const float* __restrict__ Wr) {
    int z = blockIdx.y, n = blockIdx.x, k = threadIdx.x;
    const float* W = z ? Wr : Wl;
    float x = W[(size_t)k * cD + n];
    __nv_bfloat16 hi = __float2bfloat16_rn(x);
    __nv_bfloat16 lo = __float2bfloat16_rn(x - __bfloat162float(hi));
    g_Bhi[z][n * cD + k] = hi;
    g_Blo[z][n * cD + k] = lo;
}

// ------------------------- K1: mma.sync bf16 split GEMM v4 ----------------
// Tile 128x128, grid (4 combos = nhalf+2*z, 391 m-tiles). Double-buffered
// K-chunks of 32 (8 chunks), cp.async prefetch of chunk c+1 during compute
// of chunk c. 80KB smem, launch_bounds(256,2) -> 2 CTAs/SM.
constexpr int SSTp = 40;                       // halves per smem row (80 B)
constexpr int TILEP = 128 * SSTp;              // 5120 halves = 10240 B
constexpr int STAGEB = 4 * TILEP * 2;          // 40960 B per stage
constexpr int SMEM4 = 2 * STAGEB;              // 81920 B

__global__ void __launch_bounds__(256, 2)
k_gemm3(const float* __restrict__ bl, const float* __restrict__ br) {
    extern __shared__ __nv_bfloat16 sm4[];
    const uint32_t sb = smem_u32(sm4);
    const int tid = threadIdx.x, wid = tid >> 5, lane = tid & 31;
    const int m0 = blockIdx.y * 128;
    const int nhalf = blockIdx.x & 1, z = blockIdx.x >> 1;
    const int n0 = nhalf * 128;
    const __nv_bfloat16* __restrict__ gBh = g_Bhi[z];
    const __nv_bfloat16* __restrict__ gBl = g_Blo[z];

    const int mw = (wid & 1) * 64;   // warp m offset
    const int nw = (wid >> 1) * 32;  // warp n offset
    const int aRow = mw + (lane & 15);
    const int aK = (lane >> 4) * 8;
    const int bN = ((lane >> 4) & 1) * 8 + (lane & 7);
    const int bK = ((lane >> 3) & 1) * 8;

    // per-thread staging coords: 2 rows x 4 x 16B per tile
    const int ldR = tid >> 2;        // 0..63 (row base; +64 for i=1)
    const int ldS = tid & 3;         // 16B unit within 32-half row

    auto stage_chunk = [&](int chunk, int buf) {
        const int kb = chunk * 32;
        const uint32_t base = sb + (uint32_t)buf * STAGEB;
        #pragma unroll
        for (int i = 0; i < 2; i++) {
            int r = ldR + i * 64;
            uint32_t d = (uint32_t)((r * SSTp + ldS * 8) * 2);
            size_t gsA = (size_t)(m0 + r) * cD + kb + ldS * 8;
            size_t gsB = (size_t)(n0 + r) * cD + kb + ldS * 8;
            cpa16(base + d, g_Ahi + gsA);
            cpa16(base + TILEP * 2 + d, g_Alo + gsA);
            cpa16(base + 2 * TILEP * 2 + d, gBh + gsB);
            cpa16(base + 3 * TILEP * 2 + d, gBl + gsB);
        }
        cpa_commit();
    };

    float acc[4][4][4];
    #pragma unroll
    for (int mi = 0; mi < 4; mi++)
        #pragma unroll
        for (int ni = 0; ni < 4; ni++)
            #pragma unroll
            for (int q = 0; q < 4; q++) acc[mi][ni][q] = 0.0f;

    stage_chunk(0, 0);

    #pragma unroll 1
    for (int c = 0; c < 8; c++) {
        if (c + 1 < 8) {
            stage_chunk(c + 1, (c + 1) & 1);
            cpa_wait<1>();
        } else {
            cpa_wait<0>();
        }
        __syncthreads();

        const uint32_t base = sb + (uint32_t)(c & 1) * STAGEB;
        const uint32_t uAh = base;
        const uint32_t uAl = base + TILEP * 2;
        const uint32_t uBh = base + 2 * TILEP * 2;
        const uint32_t uBl = base + 3 * TILEP * 2;

        #pragma unroll
        for (int ks = 0; ks < 2; ks++) {
            const int kk = ks * 16;
            uint32_t ah[4][4], al[4][4], bh[4][2], bl2[4][2];
            #pragma unroll
            for (int mi = 0; mi < 4; mi++) {
                uint32_t off =
                    (uint32_t)(((aRow + mi * 16) * SSTp + kk + aK) * 2);
                ldm_x4(ah[mi][0], ah[mi][1], ah[mi][2], ah[mi][3], uAh + off);
                ldm_x4(al[mi][0], al[mi][1], al[mi][2], al[mi][3], uAl + off);
            }
            #pragma unroll
            for (int nj = 0; nj < 2; nj++) {
                uint32_t off =
                    (uint32_t)(((nw + nj * 16 + bN) * SSTp + kk + bK) * 2);
                ldm_x4(bh[2 * nj][0], bh[2 * nj][1], bh[2 * nj + 1][0],
                       bh[2 * nj + 1][1], uBh + off);
                ldm_x4(bl2[2 * nj][0], bl2[2 * nj][1], bl2[2 * nj + 1][0],
                       bl2[2 * nj + 1][1], uBl + off);
            }
            #pragma unroll
            for (int mi = 0; mi < 4; mi++)
                #pragma unroll
                for (int ni = 0; ni < 4; ni++) {
                    mma16816(acc[mi][ni], ah[mi][0], ah[mi][1], ah[mi][2],
                             ah[mi][3], bh[ni][0], bh[ni][1]);
                    mma16816(acc[mi][ni], ah[mi][0], ah[mi][1], ah[mi][2],
                             ah[mi][3], bl2[ni][0], bl2[ni][1]);
                    mma16816(acc[mi][ni], al[mi][0], al[mi][1], al[mi][2],
                             al[mi][3], bh[ni][0], bh[ni][1]);
                }
        }
        __syncthreads();
    }

    const float* __restrict__ bias = z ? br : bl;
    float* __restrict__ out = z ? g_embR : g_embL;
    const int mbase = m0 + mw + (lane >> 2);
    #pragma unroll
    for (int ni = 0; ni < 4; ni++) {
        int col = n0 + nw + ni * 8 + (lane & 3) * 2;
        float2 bv = *(const float2*)(bias + col);
        #pragma unroll
        for (int mi = 0; mi < 4; mi++) {
            int mg0 = mbase + mi * 16;
            int mg1 = mg0 + 8;
            if (mg0 < cV) {
                float2 o = make_float2(acc[mi][ni][0] + bv.x,
                                       acc[mi][ni][1] + bv.y);
                *(float2*)(out + (size_t)mg0 * cD + col) = o;
            }
            if (mg1 < cV) {
                float2 o = make_float2(acc[mi][ni][2] + bv.x,
                                       acc[mi][ni][3] + bv.y);
                *(float2*)(out + (size_t)mg1 * cD + col) = o;
            }
        }
    }
}

// ------------------------- K2: edge pass 1 (w), 2 edges/warp -------------------------
__global__ void __launch_bounds__(256) k_w(const int* __restrict__ eidx,
                                           const float* __restrict__ emb) {
    int wrp = blockIdx.x * 8 + (threadIdx.x >> 5);
    int lane = threadIdx.x & 31;
    int gw0 = wrp * 2;
    int g = gw0 / cE;
    int e0 = gw0 % cE;
    const int* __restrict__ srcb = eidx + (size_t)(g * 2) * cE;
    const int* __restrict__ dstb = srcb + cE;
    int s0 = srcb[e0], s1 = srcb[e0 + 1];
    int d0 = dstb[e0], d1 = dstb[e0 + 1];
    int ts0 = g_tok[g * cL + s0], ts1 = g_tok[g * cL + s1];
    int td0 = g_tok[g * cL + d0], td1 = g_tok[g * cL + d1];
    const float4* a0p = (const float4*)(emb + (size_t)ts0 * cD);
    const float4* b0p = (const float4*)(emb + (size_t)td0 * cD);
    const float4* a1p = (const float4*)(emb + (size_t)ts1 * cD);
    const float4* b1p = (const float4*)(emb + (size_t)td1 * cD);
    float ss0 = 0.0f, ss1 = 0.0f;
    #pragma unroll
    for (int i = 0; i < 2; i++) {
        int j = lane + i * 32;
        float4 a0 = a0p[j], b0 = b0p[j], a1 = a1p[j], b1 = b1p[j];
        float x0 = a0.x - b0.x, y0 = a0.y - b0.y, z0 = a0.z - b0.z,
              w0 = a0.w - b0.w;
        float x1 = a1.x - b1.x, y1 = a1.y - b1.y, z1 = a1.z - b1.z,
              w1 = a1.w - b1.w;
        ss0 += x0 * x0 + y0 * y0 + z0 * z0 + w0 * w0;
        ss1 += x1 * x1 + y1 * y1 + z1 * z1 + w1 * w1;
    }
    warp_sum2(ss0, ss1);
    if (lane == 0) {
        g_w[gw0] = sqrtf(ss0 + 1e-12f);
        g_w[gw0 + 1] = sqrtf(ss1 + 1e-12f);
    }
}

// ------------------------- K3: beta -------------------------
__global__ void __launch_bounds__(256) k_beta() {
    int g = blockIdx.x, tid = threadIdx.x;
    __shared__ float sm[256];
    float s = 0.0f;
    for (int e = tid; e < cE; e += 256) s += g_w[g * cE + e];
    sm[tid] = s;
    __syncthreads();
    for (int o = 128; o > 0; o >>= 1) {
        if (tid < o) sm[tid] += sm[tid + o];
        __syncthreads();
    }
    if (tid == 0) g_beta[g] = sm[0] / (float)cE;
}

// ------------------------- K4: fused GAT (score+softmax+agg+pool) ----------
__global__ void __launch_bounds__(512) k_gat(const int* __restrict__ eidx,
                                             const float* __restrict__ We,
                                             const float* __restrict__ att,
                                             const float* __restrict__ gbias) {
    const int g = blockIdx.x;
    const int tid = threadIdx.x, lane = tid & 31, wrp = tid >> 5;
    __shared__ int off[cL + 1];
    __shared__ int cnt[cL];
    __shared__ int etok[cE];
    __shared__ float eew[cE];
    __shared__ float spool[cD];

    for (int i = tid; i < cL; i += 512) cnt[i] = 0;
    if (tid < cD) spool[tid] = -1e30f;
    __syncthreads();
    for (int e = tid; e < cE; e += 512) {
        int d = eidx[(size_t)(g * 2 + 1) * cE + e];
        atomicAdd(&cnt[d], 1);
    }
    __syncthreads();
    if (tid == 0) off[0] = 0;
    off[tid + 1] = cnt[tid];
    __syncthreads();
    #pragma unroll
    for (int st = 1; st < cL; st <<= 1) {
        int v = off[tid + 1];
        if (tid >= st) v += off[tid + 1 - st];
        __syncthreads();
        off[tid + 1] = v;
        __syncthreads();
    }
    cnt[tid] = 0;
    __syncthreads();
    {
        float beta = g_beta[g];
        float c = -0.5f / (beta * beta);
        for (int e = tid; e < cE; e += 512) {
            int d = eidx[(size_t)(g * 2 + 1) * cE + e];
            int s = eidx[(size_t)(g * 2) * cE + e];
            int pos = off[d] + atomicAdd(&cnt[d], 1);
            etok[pos] = g_tok[g * cL + s];
            float w = g_w[g * cE + e];
            eew[pos] = __expf(w * w * c);
        }
    }
    __syncthreads();

    const int q0 = lane * 4, q1 = 128 + lane * 4;
    const float4 We0 = *(const float4*)(We + q0);
    const float4 We1 = *(const float4*)(We + q1);
    const float4 at0 = *(const float4*)(att + q0);
    const float4 at1 = *(const float4*)(att + q1);
    const float4 gb0 = *(const float4*)(gbias + q0);
    const float4 gb1 = *(const float4*)(gbias + q1);
    float4 pm0 = make_float4(-1e30f, -1e30f, -1e30f, -1e30f);
    float4 pm1 = pm0;

    for (int dst = wrp; dst < cL; dst += 16) {
        int tokd = g_tok[g * cL + dst];
        const float4 xr0 = *(const float4*)(g_embR + (size_t)tokd * cD + q0);
        const float4 xr1 = *(const float4*)(g_embR + (size_t)tokd * cD + q1);
        float m = -1e30f, den = 0.0f;
        float4 a0 = make_float4(0.f, 0.f, 0.f, 0.f), a1 = a0;
        const int pend = off[dst + 1];
        int p = off[dst];
        for (; p + 1 < pend; p += 2) {
            int tA = etok[p], tB = etok[p + 1];
            float ewA = eew[p], ewB = eew[p + 1];
            const float4 xA0 = *(const float4*)(g_embL + (size_t)tA * cD + q0);
            const float4 xA1 = *(const float4*)(g_embL + (size_t)tA * cD + q1);
            const float4 xB0 = *(const float4*)(g_embL + (size_t)tB * cD + q0);
            const float4 xB1 = *(const float4*)(g_embL + (size_t)tB * cD + q1);
            float vx, pa = 0.0f, pb = 0.0f;
            vx = xA0.x + xr0.x + ewA * We0.x; pa += (vx > 0.f ? vx : 0.2f * vx) * at0.x;
            vx = xA0.y + xr0.y + ewA * We0.y; pa += (vx > 0.f ? vx : 0.2f * vx) * at0.y;
            vx = xA0.z + xr0.z + ewA * We0.z; pa += (vx > 0.f ? vx : 0.2f * vx) * at0.z;
            vx = xA0.w + xr0.w + ewA * We0.w; pa += (vx > 0.f ? vx : 0.2f * vx) * at0.w;
            vx = xA1.x + xr1.x + ewA * We1.x; pa += (vx > 0.f ? vx : 0.2f * vx) * at1.x;
            vx = xA1.y + xr1.y + ewA * We1.y; pa += (vx > 0.f ? vx : 0.2f * vx) * at1.y;
            vx = xA1.z + xr1.z + ewA * We1.z; pa += (vx > 0.f ? vx : 0.2f * vx) * at1.z;
            vx = xA1.w + xr1.w + ewA * We1.w; pa += (vx > 0.f ? vx : 0.2f * vx) * at1.w;
            vx = xB0.x + xr0.x + ewB * We0.x; pb += (vx > 0.f ? vx : 0.2f * vx) * at0.x;
            vx = xB0.y + xr0.y + ewB * We0.y; pb += (vx > 0.f ? vx : 0.2f * vx) * at0.y;
            vx = xB0.z + xr0.z + ewB * We0.z; pb += (vx > 0.f ? vx : 0.2f * vx) * at0.z;
            vx = xB0.w + xr0.w + ewB * We0.w; pb += (vx > 0.f ? vx : 0.2f * vx) * at0.w;
            vx = xB1.x + xr1.x + ewB * We1.x; pb += (vx > 0.f ? vx : 0.2f * vx) * at1.x;
            vx = xB1.y + xr1.y + ewB * We1.y; pb += (vx > 0.f ? vx : 0.2f * vx) * at1.y;
            vx = xB1.z + xr1.z + ewB * We1.z; pb += (vx > 0.f ? vx : 0.2f * vx) * at1.z;
            vx = xB1.w + xr1.w + ewB * We1.w; pb += (vx > 0.f ? vx : 0.2f * vx) * at1.w;
            warp_sum2(pa, pb);
            float mn = fmaxf(m, fmaxf(pa, pb));
            float sc = __expf(m - mn);
            float eA = __expf(pa - mn);
            float eB = __expf(pb - mn);
            den = den * sc + eA + eB;
            a0.x = a0.x * sc + eA * xA0.x + eB * xB0.x;
            a0.y = a0.y * sc + eA * xA0.y + eB * xB0.y;
            a0.z = a0.z * sc + eA * xA0.z + eB * xB0.z;
            a0.w = a0.w * sc + eA * xA0.w + eB * xB0.w;
            a1.x = a1.x * sc + eA * xA1.x + eB * xB1.x;
            a1.y = a1.y * sc + eA * xA1.y + eB * xB1.y;
            a1.z = a1.z * sc + eA * xA1.z + eB * xB1.z;
            a1.w = a1.w * sc + eA * xA1.w + eB * xB1.w;
            m = mn;
        }
        if (p < pend) {
            int tok = etok[p];
            float ew = eew[p];
            const float4 x0 = *(const float4*)(g_embL + (size_t)tok * cD + q0);
            const float4 x1 = *(const float4*)(g_embL + (size_t)tok * cD + q1);
            float vx, par = 0.0f;
            vx = x0.x + xr0.x + ew * We0.x; par += (vx > 0.f ? vx : 0.2f * vx) * at0.x;
            vx = x0.y + xr0.y + ew * We0.y; par += (vx > 0.f ? vx : 0.2f * vx) * at0.y;
            vx = x0.z + xr0.z + ew * We0.z; par += (vx > 0.f ? vx : 0.2f * vx) * at0.z;
            vx = x0.w + xr0.w + ew * We0.w; par += (vx > 0.f ? vx : 0.2f * vx) * at0.w;
            vx = x1.x + xr1.x + ew * We1.x; par += (vx > 0.f ? vx : 0.2f * vx) * at1.x;
            vx = x1.y + xr1.y + ew * We1.y; par += (vx > 0.f ? vx : 0.2f * vx) * at1.y;
            vx = x1.z + xr1.z + ew * We1.z; par += (vx > 0.f ? vx : 0.2f * vx) * at1.z;
            vx = x1.w + xr1.w + ew * We1.w; par += (vx > 0.f ? vx : 0.2f * vx) * at1.w;
            float s = warp_sum(par);
            float mn = fmaxf(m, s);
            float sc = __expf(m - mn);
            float pe = __expf(s - mn);
            den = den * sc + pe;
            a0.x = a0.x * sc + pe * x0.x; a0.y = a0.y * sc + pe * x0.y;
            a0.z = a0.z * sc + pe * x0.z; a0.w = a0.w * sc + pe * x0.w;
            a1.x = a1.x * sc + pe * x1.x; a1.y = a1.y * sc + pe * x1.y;
            a1.z = a1.z * sc + pe * x1.z; a1.w = a1.w * sc + pe * x1.w;
        }
        float inv = 1.0f / (den + 1e-16f);
        pm0.x = fmaxf(pm0.x, a0.x * inv + gb0.x);
        pm0.y = fmaxf(pm0.y, a0.y * inv + gb0.y);
        pm0.z = fmaxf(pm0.z, a0.z * inv + gb0.z);
        pm0.w = fmaxf(pm0.w, a0.w * inv + gb0.w);
        pm1.x = fmaxf(pm1.x, a1.x * inv + gb1.x);
        pm1.y = fmaxf(pm1.y, a1.y * inv + gb1.y);
        pm1.z = fmaxf(pm1.z, a1.z * inv + gb1.z);
        pm1.w = fmaxf(pm1.w, a1.w * inv + gb1.w);
    }
    atomicMaxF(&spool[q0 + 0], pm0.x);
    atomicMaxF(&spool[q0 + 1], pm0.y);
    atomicMaxF(&spool[q0 + 2], pm0.z);
    atomicMaxF(&spool[q0 + 3], pm0.w);
    atomicMaxF(&spool[q1 + 0], pm1.x);
    atomicMaxF(&spool[q1 + 1], pm1.y);
    atomicMaxF(&spool[q1 + 2], pm1.z);
    atomicMaxF(&spool[q1 + 3], pm1.w);
    __syncthreads();
    if (tid < cD) g_pooled[g * cD + tid] = spool[tid];
}

// ------------------------- K7: GRU input gates (Wih streamed once/block) ---
__global__ void __launch_bounds__(256) k_gi(const float* __restrict__ Wihf,
                                            const float* __restrict__ bihf,
                                            const float* __restrict__ Wihb,
                                            const float* __restrict__ bihb) {
    const int rg = blockIdx.x, dir = blockIdx.y, tid = threadIdx.x;
    const float* __restrict__ Wih = dir ? Wihb : Wihf;
    const float* __restrict__ bih = dir ? bihb : bihf;
    __shared__ float xs[8][cD];
    for (int i = tid; i < 8 * cD; i += 256) {
        int r = i >> 8, k = i & 255;
        int rr = rg * 8 + r;
        int t = rr / cB, b = rr % cB;
        xs[r][k] = g_pooled[(b * cT + t) * cD + k];
    }
    __syncthreads();
    #pragma unroll
    for (int q = 0; q < 3; q++) {
        int j = q * 256 + tid;
        float acc[8];
        float bj = bih[j];
        #pragma unroll
        for (int r = 0; r < 8; r++) acc[r] = bj;
        const float4* wr = (const float4*)(Wih + (size_t)j * cD);
        #pragma unroll 8
        for (int k4 = 0; k4 < 64; k4++) {
            float4 wv = wr[k4];
            #pragma unroll
            for (int r = 0; r < 8; r++) {
                float4 xx = *(const float4*)&xs[r][k4 * 4];
                acc[r] += wv.x * xx.x + wv.y * xx.y + wv.z * xx.z + wv.w * xx.w;
            }
        }
        #pragma unroll
        for (int r = 0; r < 8; r++)
            g_gi[dir][(size_t)(rg * 8 + r) * 768 + j] = acc[r];
    }
}

// ------------------------- K8: fused GRU (all 8 steps, 1 launch) ----------
__global__ void __launch_bounds__(256) k_gru(const float* __restrict__ Whhf,
                                             const float* __restrict__ bhhf,
                                             const float* __restrict__ Whhb,
                                             const float* __restrict__ bhhb) {
    const int dir = blockIdx.y;
    const int tid = threadIdx.x;
    const int b = tid & 15;
    const int jt = tid >> 4;
    const int i = blockIdx.x * 16 + jt;

    const float* __restrict__ Whh = dir ? Whhb : Whhf;
    const float* __restrict__ bhh = dir ? bhhb : bhhf;
    const float bh0 = bhh[i], bh1 = bhh[i + 256], bh2 = bhh[i + 512];
    const float4* w0 = (const float4*)(Whh + (size_t)i * cD);
    const float4* w1 = (const float4*)(Whh + (size_t)(i + 256) * cD);
    const float4* w2 = (const float4*)(Whh + (size_t)(i + 512) * cD);

    __shared__ float h[cB * cH];

    for (int step = 0; step < cT; step++) {
        const int t = (dir == 0) ? step : (cT - 1 - step);
        const int pin = step & 1, pout = (step + 1) & 1;
        for (int idx = tid; idx < cB * cH; idx += 256)
            h[idx] = g_h[dir][pin][idx];
        __syncthreads();

        const float4* hv = (const float4*)(h + b * cH);
        float hr = 0.0f, hz = 0.0f, hn = 0.0f;
        #pragma unroll 4
        for (int k4 = 0; k4 < 64; k4++) {
            float4 hh = hv[k4];
            float4 a = w0[k4], c = w1[k4], d = w2[k4];
            hr += a.x * hh.x + a.y * hh.y + a.z * hh.z + a.w * hh.w;
            hz += c.x * hh.x + c.y * hh.y + c.z * hh.z + c.w * hh.w;
            hn += d.x * hh.x + d.y * hh.y + d.z * hh.z + d.w * hh.w;
        }
        hr += bh0; hz += bh1; hn += bh2;

        const float* gi = &g_gi[dir][(size_t)(t * cB + b) * 768];
        float r = sigmoidf_(gi[i] + hr);
        float z = sigmoidf_(gi[i + 256] + hz);
        float n = tanhf(gi[i + 512] + r * hn);
        float hp = h[b * cH + i];
        float hnew = (1.0f - z) * n + z * hp;

        g_ys[dir][(size_t)(t * cB + b) * cH + i] = hnew;
        g_h[dir][pout][b * cH + i] = hnew;
        __syncthreads();

        if (step < cT - 1) {
            if (tid == 0) {
                __threadfence();
                unsigned tk = atomicAdd(&g_grubar[dir], 1u);
                unsigned target = (tk / 16u + 1u) * 16u;
                while (atomicAdd(&g_grubar[dir], 0u) < target) {}
                __threadfence();
            }
            __syncthreads();
        }
    }
}

// ------------------------- K9: finalize output -------------------------
__global__ void __launch_bounds__(256) k_fin(float* __restrict__ out) {
    int idx = blockIdx.x * 256 + threadIdx.x;
    const int n1 = cT * cB * cH;
    const int n2 = n1 + cB * cH;
    if (idx < n1) {
        out[idx] = g_ys[0][idx] + g_ys[1][idx];
    } else if (idx < n2) {
        out[idx] = g_ys[0][(cT - 1) * cB * cH + (idx - n1)];
    } else {
        out[idx] = g_ys[1][idx - n2];
    }
}

// ------------------------- launch -------------------------
extern "C" void kernel_launch(void* const* d_in, const int* in_sizes, int n_in,
                              void* d_out, int out_size) {
    const int*   token_ids = (const int*)d_in[0];
    const int*   edge_index = (const int*)d_in[1];
    const float* emb  = (const float*)d_in[2];
    const float* Wl   = (const float*)d_in[3];
    const float* bl   = (const float*)d_in[4];
    const float* Wr   = (const float*)d_in[5];
    const float* br   = (const float*)d_in[6];
    const float* We   = (const float*)d_in[7];
    const float* att  = (const float*)d_in[8];
    const float* gbias = (const float*)d_in[9];
    const float* Wihf = (const float*)d_in[10];
    const float* Whhf = (const float*)d_in[11];
    const float* bihf = (const float*)d_in[12];
    const float* bhhf = (const float*)d_in[13];
    const float* Wihb = (const float*)d_in[14];
    const float* Whhb = (const float*)d_in[15];
    const float* bihb = (const float*)d_in[16];
    const float* bhhb = (const float*)d_in[17];
    float* out = (float*)d_out;

    static cudaStream_t s2 = nullptr;
    static cudaEvent_t evF = nullptr, evJ = nullptr;
    if (s2 == nullptr) {
        cudaStreamCreateWithFlags(&s2, cudaStreamNonBlocking);
        cudaEventCreateWithFlags(&evF, cudaEventDisableTiming);
        cudaEventCreateWithFlags(&evJ, cudaEventDisableTiming);
    }
    cudaFuncSetAttribute(k_gemm3,
                         cudaFuncAttributeMaxDynamicSharedMemorySize, SMEM4);

    // k_gemm3 stays launch #4 for ncu visibility.
    k_tok<<<cG, cL>>>(token_ids);                                     // #1
    cudaEventRecord(evF, 0);
    k_splitA<<<(int)(((size_t)cVp * cD) / (256 * 8)), 256>>>(emb);    // #2
    k_splitB<<<dim3(cD, 2), cD>>>(Wl, Wr);                            // #3
    k_gemm3<<<dim3(4, cVp / 128), 256, SMEM4>>>(bl, br);              // #4
    // side stream: w + beta overlap the split/gemm chain
    cudaStreamWaitEvent(s2, evF, 0);
    k_w<<<cG * cE / 16, 256, 0, s2>>>(edge_index, emb);               // #5
    k_beta<<<cG, 256, 0, s2>>>();                                     // #6
    cudaEventRecord(evJ, s2);

    k_zero<<<64, 256>>>();                                            // #7
    cudaStreamWaitEvent(0, evJ, 0);
    k_gat<<<cG, 512>>>(edge_index, We, att, gbias);                   // #8
    k_gi<<<dim3(16, 2), 256>>>(Wihf, bihf, Wihb, bihb);               // #9
    k_gru<<<dim3(16, 2), 256>>>(Whhf, bhhf, Whhb, bhhb);              // #10
    k_fin<<<160, 256>>>(out);                                         // #11
}

// round 12
// speedup vs baseline: 1.0831x; 1.0831x over previous
#include <cuda_runtime.h>
#include <cuda_bf16.h>
#include <cstdint>
#include <math.h>

// Problem constants (fixed by the dataset)
constexpr int cV = 50000;   // vocab
constexpr int cVp = 50048;  // vocab padded to 391*128
constexpr int cD = 256;     // embedding dim
constexpr int cH = 256;     // GRU hidden
constexpr int cB = 16;      // batch
constexpr int cT = 8;       // num_subtrees (time steps)
constexpr int cL = 512;     // subtree_len (nodes per graph)
constexpr int cE = 2048;    // edges per graph
constexpr int cG = cB * cT; // graphs = 128
constexpr int cNW = cVp / 32;  // 1564 bitmap words

// ------------------------- device scratch -------------------------
__device__ float g_embL[(size_t)cVp * cD];  // compact rows: emb@Wl + bl
__device__ float g_embR[(size_t)cVp * cD];
__device__ __nv_bfloat16 g_Ahi[(size_t)cVp * cD];
__device__ __nv_bfloat16 g_Alo[(size_t)cVp * cD];
__device__ __nv_bfloat16 g_Bhi[2][cD * cD];  // W^T split hi: [z][n][k]
__device__ __nv_bfloat16 g_Blo[2][cD * cD];
__device__ int   g_tok[cG * cL];            // original token ids
__device__ int   g_ctok[cG * cL];           // compact token ids
__device__ unsigned g_used[cNW];            // vocab bitmap (idempotent)
__device__ unsigned g_wb[cNW];              // exclusive rank base per word
__device__ int   g_NU;                      // number of used tokens
__device__ int   g_origrow[cVp];            // compact id -> vocab id
__device__ float g_w[cG * cE];
__device__ float g_beta[cG];
__device__ float g_pooled[cG * cD];
__device__ float g_gi[2][cT * cB * 3 * cH];
__device__ float g_h[2][2][cB * cH];        // [dir][parity][b*H]
__device__ float g_ys[2][cT * cB * cH];
__device__ unsigned g_grubar[2];            // GRU inter-CTA barrier tickets

// ------------------------- small utils -------------------------
__device__ __forceinline__ float warp_sum(float v) {
    #pragma unroll
    for (int o = 16; o > 0; o >>= 1) v += __shfl_xor_sync(0xffffffffu, v, o);
    return v;
}
__device__ __forceinline__ void warp_sum2(float& v0, float& v1) {
    #pragma unroll
    for (int o = 16; o > 0; o >>= 1) {
        v0 += __shfl_xor_sync(0xffffffffu, v0, o);
        v1 += __shfl_xor_sync(0xffffffffu, v1, o);
    }
}
__device__ __forceinline__ void atomicMaxF(float* addr, float val) {
    int* ia = (int*)addr;
    int old = __float_as_int(*addr);
    while (__int_as_float(old) < val) {
        int prev = atomicCAS(ia, old, __float_as_int(val));
        if (prev == old) break;
        old = prev;
    }
}
__device__ __forceinline__ float sigmoidf_(float x) { return 1.0f / (1.0f + expf(-x)); }
__device__ __forceinline__ int tok_rank(int tok) {
    int word = tok >> 5, bit = tok & 31;
    return (int)g_wb[word] + __popc(g_used[word] & ((1u << bit) - 1u));
}

// ------------------------- mma.sync helpers -------------------------
__device__ __forceinline__ uint32_t smem_u32(const void* p) {
    uint32_t a;
    asm("{ .reg .u64 t; cvta.to.shared.u64 t, %1; cvt.u32.u64 %0, t; }"
        : "=r"(a) : "l"(p));
    return a;
}
__device__ __forceinline__ void ldm_x4(uint32_t& r0, uint32_t& r1, uint32_t& r2,
                                       uint32_t& r3, uint32_t addr) {
    asm volatile("ldmatrix.sync.aligned.m8n8.x4.shared.b16 {%0,%1,%2,%3}, [%4];"
                 : "=r"(r0), "=r"(r1), "=r"(r2), "=r"(r3) : "r"(addr));
}
__device__ __forceinline__ void mma16816(float* d, uint32_t a0, uint32_t a1,
                                         uint32_t a2, uint32_t a3,
                                         uint32_t b0, uint32_t b1) {
    asm volatile(
        "mma.sync.aligned.m16n8k16.row.col.f32.bf16.bf16.f32 "
        "{%0,%1,%2,%3}, {%4,%5,%6,%7}, {%8,%9}, {%0,%1,%2,%3};"
        : "+f"(d[0]), "+f"(d[1]), "+f"(d[2]), "+f"(d[3])
        : "r"(a0), "r"(a1), "r"(a2), "r"(a3), "r"(b0), "r"(b1));
}
__device__ __forceinline__ void cpa16(uint32_t dst, const void* src) {
    asm volatile("cp.async.cg.shared.global [%0], [%1], 16;" :: "r"(dst),
                 "l"(src));
}
__device__ __forceinline__ void cpa_commit() {
    asm volatile("cp.async.commit_group;" ::: "memory");
}
__device__ __forceinline__ void cpa_wait0() {
    asm volatile("cp.async.wait_group 0;" ::: "memory");
}

// ------------------------- K0: token LUT + used bitmap -------------------------
__global__ void k_tok(const int* __restrict__ token_ids) {
    int g = blockIdx.x, l = threadIdx.x;
    int b = g / cT, t = g % cT;
    int tok = token_ids[(t * cL + l) * cB + b];
    g_tok[g * cL + l] = tok;
    atomicOr(&g_used[tok >> 5], 1u << (tok & 31));  // idempotent across replays
}

// scan bitmap popcounts -> per-word exclusive base + total count
__global__ void __launch_bounds__(512) k_scan() {
    __shared__ unsigned ts[512];
    const int tid = threadIdx.x;
    unsigned loc[4];
    unsigned s = 0;
    #pragma unroll
    for (int i = 0; i < 4; i++) {
        int w = tid * 4 + i;
        loc[i] = s;
        if (w < cNW) s += (unsigned)__popc(g_used[w]);
    }
    ts[tid] = s;
    __syncthreads();
    for (int off = 1; off < 512; off <<= 1) {
        unsigned v = (tid >= off) ? ts[tid - off] : 0u;
        __syncthreads();
        ts[tid] += v;
        __syncthreads();
    }
    unsigned base = tid ? ts[tid - 1] : 0u;
    #pragma unroll
    for (int i = 0; i < 4; i++) {
        int w = tid * 4 + i;
        if (w < cNW) g_wb[w] = base + loc[i];
    }
    if (tid == 511) g_NU = (int)ts[511];
}

// compact id -> vocab id
__global__ void __launch_bounds__(256) k_remap() {
    int v = blockIdx.x * 256 + threadIdx.x;
    if (v >= cV) return;
    unsigned bits = g_used[v >> 5];
    int bit = v & 31;
    if ((bits >> bit) & 1u) {
        int rank = (int)g_wb[v >> 5] + __popc(bits & ((1u << bit) - 1u));
        g_origrow[rank] = v;
    }
}

// per-node compact token
__global__ void __launch_bounds__(256) k_ctok() {
    int i = blockIdx.x * 256 + threadIdx.x;  // 256 blocks x 256 = 65536
    g_ctok[i] = tok_rank(g_tok[i]);
}

__global__ void k_zero() {
    int idx = blockIdx.x * 256 + threadIdx.x;
    ((float*)g_h)[idx] = 0.0f;
}

// ------------------------- split-precision conversion (gathered) ----------
__global__ void __launch_bounds__(256) k_splitA(const float* __restrict__ emb) {
    size_t idx = ((size_t)blockIdx.x * 256 + threadIdx.x) * 8;
    int row = (int)(idx >> 8);            // compact row id
    int col = (int)(idx & 255);
    int nu = g_NU;
    float v[8];
    if (row < nu) {
        size_t src = (size_t)g_origrow[row] * cD + col;
        float4 a = *(const float4*)(emb + src);
        float4 b = *(const float4*)(emb + src + 4);
        v[0] = a.x; v[1] = a.y; v[2] = a.z; v[3] = a.w;
        v[4] = b.x; v[5] = b.y; v[6] = b.z; v[7] = b.w;
    } else {
        #pragma unroll
        for (int i = 0; i < 8; i++) v[i] = 0.0f;
    }
    __nv_bfloat16 hi[8], lo[8];
    #pragma unroll
    for (int i = 0; i < 8; i++) {
        hi[i] = __float2bfloat16_rn(v[i]);
        lo[i] = __float2bfloat16_rn(v[i] - __bfloat162float(hi[i]));
    }
    *(uint4*)(g_Ahi + idx) = *(uint4*)hi;
    *(uint4*)(g_Alo + idx) = *(uint4*)lo;
}

// W -> W^T hi/lo bf16 (B operand is [n][k], K-contiguous)
__global__ void __launch_bounds__(256) k_splitB(const float* __restrict__ Wl,
                                                const float* __restrict__ Wr) {
    int z = blockIdx.y, n = blockIdx.x, k = threadIdx.x;
    const float* W = z ? Wr : Wl;
    float x = W[(size_t)k * cD + n];
    __nv_bfloat16 hi = __float2bfloat16_rn(x);
    __nv_bfloat16 lo = __float2bfloat16_rn(x - __bfloat162float(hi));
    g_Bhi[z][n * cD + k] = hi;
    g_Blo[z][n * cD + k] = lo;
}

// ------------------------- K1: mma.sync bf16 split GEMM (R9 config) -------
// Tile 128x128, grid (4 combos = nhalf+2*z, 391 m-tiles). 72KB smem,
// launch_bounds(256,2) -> 2 CTAs/SM. K chunks of 64 staged via cp.async.
// CTAs whose m-tile is entirely past g_NU exit immediately.
constexpr int SST = 72;                       // halves per smem row (144B)
constexpr int TILE3 = 128 * SST;              // halves per tile
constexpr int SMEM3 = 4 * TILE3 * 2;          // 73728 B

__global__ void __launch_bounds__(256, 2)
k_gemm3(const float* __restrict__ bl, const float* __restrict__ br) {
    const int m0 = blockIdx.y * 128;
    if (m0 >= g_NU) return;                   // compacted: nothing to do

    extern __shared__ __nv_bfloat16 sm3[];
    const uint32_t sb = smem_u32(sm3);
    const uint32_t uAh = sb;
    const uint32_t uAl = sb + TILE3 * 2;
    const uint32_t uBh = sb + 2 * TILE3 * 2;
    const uint32_t uBl = sb + 3 * TILE3 * 2;

    const int tid = threadIdx.x, wid = tid >> 5, lane = tid & 31;
    const int nhalf = blockIdx.x & 1, z = blockIdx.x >> 1;
    const int n0 = nhalf * 128;
    const __nv_bfloat16* __restrict__ gBh = g_Bhi[z];
    const __nv_bfloat16* __restrict__ gBl = g_Blo[z];

    const int mw = (wid & 1) * 64;   // warp m offset
    const int nw = (wid >> 1) * 32;  // warp n offset
    const int aRow = mw + (lane & 15);
    const int aK = (lane >> 4) * 8;
    const int bN = ((lane >> 4) & 1) * 8 + (lane & 7);
    const int bK = ((lane >> 3) & 1) * 8;

    float acc[4][4][4];
    #pragma unroll
    for (int mi = 0; mi < 4; mi++)
        #pragma unroll
        for (int ni = 0; ni < 4; ni++)
            #pragma unroll
            for (int q = 0; q < 4; q++) acc[mi][ni][q] = 0.0f;

    for (int kb = 0; kb < 256; kb += 64) {
        #pragma unroll
        for (int i = 0; i < 4; i++) {
            int idx = tid + i * 256;
            int r = idx >> 3, s = idx & 7;
            size_t gs = (size_t)(m0 + r) * cD + kb + s * 8;
            uint32_t d = (uint32_t)((r * SST + s * 8) * 2);
            cpa16(uAh + d, g_Ahi + gs);
            cpa16(uAl + d, g_Alo + gs);
        }
        #pragma unroll
        for (int i = 0; i < 4; i++) {
            int idx = tid + i * 256;
            int r = idx >> 3, s = idx & 7;
            size_t gs = (size_t)(n0 + r) * cD + kb + s * 8;
            uint32_t d = (uint32_t)((r * SST + s * 8) * 2);
            cpa16(uBh + d, gBh + gs);
            cpa16(uBl + d, gBl + gs);
        }
        cpa_commit();
        cpa_wait0();
        __syncthreads();

        #pragma unroll
        for (int ks = 0; ks < 4; ks++) {
            const int kk = ks * 16;
            uint32_t ah[4][4], al[4][4], bh[4][2], bl2[4][2];
            #pragma unroll
            for (int mi = 0; mi < 4; mi++) {
                uint32_t off =
                    (uint32_t)(((aRow + mi * 16) * SST + kk + aK) * 2);
                ldm_x4(ah[mi][0], ah[mi][1], ah[mi][2], ah[mi][3], uAh + off);
                ldm_x4(al[mi][0], al[mi][1], al[mi][2], al[mi][3], uAl + off);
            }
            #pragma unroll
            for (int nj = 0; nj < 2; nj++) {
                uint32_t off =
                    (uint32_t)(((nw + nj * 16 + bN) * SST + kk + bK) * 2);
                ldm_x4(bh[2 * nj][0], bh[2 * nj][1], bh[2 * nj + 1][0],
                       bh[2 * nj + 1][1], uBh + off);
                ldm_x4(bl2[2 * nj][0], bl2[2 * nj][1], bl2[2 * nj + 1][0],
                       bl2[2 * nj + 1][1], uBl + off);
            }
            #pragma unroll
            for (int mi = 0; mi < 4; mi++)
                #pragma unroll
                for (int ni = 0; ni < 4; ni++) {
                    mma16816(acc[mi][ni], ah[mi][0], ah[mi][1], ah[mi][2],
                             ah[mi][3], bh[ni][0], bh[ni][1]);
                    mma16816(acc[mi][ni], ah[mi][0], ah[mi][1], ah[mi][2],
                             ah[mi][3], bl2[ni][0], bl2[ni][1]);
                    mma16816(acc[mi][ni], al[mi][0], al[mi][1], al[mi][2],
                             al[mi][3], bh[ni][0], bh[ni][1]);
                }
        }
        __syncthreads();
    }

    const float* __restrict__ bias = z ? br : bl;
    float* __restrict__ out = z ? g_embR : g_embL;
    const int mbase = m0 + mw + (lane >> 2);
    #pragma unroll
    for (int ni = 0; ni < 4; ni++) {
        int col = n0 + nw + ni * 8 + (lane & 3) * 2;
        float2 bv = *(const float2*)(bias + col);
        #pragma unroll
        for (int mi = 0; mi < 4; mi++) {
            int mg0 = mbase + mi * 16;
            int mg1 = mg0 + 8;
            float2 o0 = make_float2(acc[mi][ni][0] + bv.x,
                                    acc[mi][ni][1] + bv.y);
            *(float2*)(out + (size_t)mg0 * cD + col) = o0;
            float2 o1 = make_float2(acc[mi][ni][2] + bv.x,
                                    acc[mi][ni][3] + bv.y);
            *(float2*)(out + (size_t)mg1 * cD + col) = o1;
        }
    }
}

// ------------------------- K2: edge pass 1 (w), 2 edges/warp -------------------------
__global__ void __launch_bounds__(256) k_w(const int* __restrict__ eidx,
                                           const float* __restrict__ emb) {
    int wrp = blockIdx.x * 8 + (threadIdx.x >> 5);
    int lane = threadIdx.x & 31;
    int gw0 = wrp * 2;
    int g = gw0 / cE;
    int e0 = gw0 % cE;
    const int* __restrict__ srcb = eidx + (size_t)(g * 2) * cE;
    const int* __restrict__ dstb = srcb + cE;
    int s0 = srcb[e0], s1 = srcb[e0 + 1];
    int d0 = dstb[e0], d1 = dstb[e0 + 1];
    int ts0 = g_tok[g * cL + s0], ts1 = g_tok[g * cL + s1];
    int td0 = g_tok[g * cL + d0], td1 = g_tok[g * cL + d1];
    const float4* a0p = (const float4*)(emb + (size_t)ts0 * cD);
    const float4* b0p = (const float4*)(emb + (size_t)td0 * cD);
    const float4* a1p = (const float4*)(emb + (size_t)ts1 * cD);
    const float4* b1p = (const float4*)(emb + (size_t)td1 * cD);
    float ss0 = 0.0f, ss1 = 0.0f;
    #pragma unroll
    for (int i = 0; i < 2; i++) {
        int j = lane + i * 32;
        float4 a0 = a0p[j], b0 = b0p[j], a1 = a1p[j], b1 = b1p[j];
        float x0 = a0.x - b0.x, y0 = a0.y - b0.y, z0 = a0.z - b0.z,
              w0 = a0.w - b0.w;
        float x1 = a1.x - b1.x, y1 = a1.y - b1.y, z1 = a1.z - b1.z,
              w1 = a1.w - b1.w;
        ss0 += x0 * x0 + y0 * y0 + z0 * z0 + w0 * w0;
        ss1 += x1 * x1 + y1 * y1 + z1 * z1 + w1 * w1;
    }
    warp_sum2(ss0, ss1);
    if (lane == 0) {
        g_w[gw0] = sqrtf(ss0 + 1e-12f);
        g_w[gw0 + 1] = sqrtf(ss1 + 1e-12f);
    }
}

// ------------------------- K3: beta -------------------------
__global__ void __launch_bounds__(256) k_beta() {
    int g = blockIdx.x, tid = threadIdx.x;
    __shared__ float sm[256];
    float s = 0.0f;
    for (int e = tid; e < cE; e += 256) s += g_w[g * cE + e];
    sm[tid] = s;
    __syncthreads();
    for (int o = 128; o > 0; o >>= 1) {
        if (tid < o) sm[tid] += sm[tid + o];
        __syncthreads();
    }
    if (tid == 0) g_beta[g] = sm[0] / (float)cE;
}

// ------------------------- K4: fused GAT (score+softmax+agg+pool) ----------
// Uses compact token ids into g_embL/g_embR.
__global__ void __launch_bounds__(512) k_gat(const int* __restrict__ eidx,
                                             const float* __restrict__ We,
                                             const float* __restrict__ att,
                                             const float* __restrict__ gbias) {
    const int g = blockIdx.x;
    const int tid = threadIdx.x, lane = tid & 31, wrp = tid >> 5;
    __shared__ int off[cL + 1];
    __shared__ int cnt[cL];
    __shared__ int etok[cE];
    __shared__ float eew[cE];
    __shared__ float spool[cD];

    for (int i = tid; i < cL; i += 512) cnt[i] = 0;
    if (tid < cD) spool[tid] = -1e30f;
    __syncthreads();
    for (int e = tid; e < cE; e += 512) {
        int d = eidx[(size_t)(g * 2 + 1) * cE + e];
        atomicAdd(&cnt[d], 1);
    }
    __syncthreads();
    if (tid == 0) off[0] = 0;
    off[tid + 1] = cnt[tid];
    __syncthreads();
    #pragma unroll
    for (int st = 1; st < cL; st <<= 1) {
        int v = off[tid + 1];
        if (tid >= st) v += off[tid + 1 - st];
        __syncthreads();
        off[tid + 1] = v;
        __syncthreads();
    }
    cnt[tid] = 0;
    __syncthreads();
    {
        float beta = g_beta[g];
        float c = -0.5f / (beta * beta);
        for (int e = tid; e < cE; e += 512) {
            int d = eidx[(size_t)(g * 2 + 1) * cE + e];
            int s = eidx[(size_t)(g * 2) * cE + e];
            int pos = off[d] + atomicAdd(&cnt[d], 1);
            etok[pos] = g_ctok[g * cL + s];
            float w = g_w[g * cE + e];
            eew[pos] = __expf(w * w * c);
        }
    }
    __syncthreads();

    const int q0 = lane * 4, q1 = 128 + lane * 4;
    const float4 We0 = *(const float4*)(We + q0);
    const float4 We1 = *(const float4*)(We + q1);
    const float4 at0 = *(const float4*)(att + q0);
    const float4 at1 = *(const float4*)(att + q1);
    const float4 gb0 = *(const float4*)(gbias + q0);
    const float4 gb1 = *(const float4*)(gbias + q1);
    float4 pm0 = make_float4(-1e30f, -1e30f, -1e30f, -1e30f);
    float4 pm1 = pm0;

    for (int dst = wrp; dst < cL; dst += 16) {
        int tokd = g_ctok[g * cL + dst];
        const float4 xr0 = *(const float4*)(g_embR + (size_t)tokd * cD + q0);
        const float4 xr1 = *(const float4*)(g_embR + (size_t)tokd * cD + q1);
        float m = -1e30f, den = 0.0f;
        float4 a0 = make_float4(0.f, 0.f, 0.f, 0.f), a1 = a0;
        const int pend = off[dst + 1];
        int p = off[dst];
        for (; p + 1 < pend; p += 2) {
            int tA = etok[p], tB = etok[p + 1];
            float ewA = eew[p], ewB = eew[p + 1];
            const float4 xA0 = *(const float4*)(g_embL + (size_t)tA * cD + q0);
            const float4 xA1 = *(const float4*)(g_embL + (size_t)tA * cD + q1);
            const float4 xB0 = *(const float4*)(g_embL + (size_t)tB * cD + q0);
            const float4 xB1 = *(const float4*)(g_embL + (size_t)tB * cD + q1);
            float vx, pa = 0.0f, pb = 0.0f;
            vx = xA0.x + xr0.x + ewA * We0.x; pa += (vx > 0.f ? vx : 0.2f * vx) * at0.x;
            vx = xA0.y + xr0.y + ewA * We0.y; pa += (vx > 0.f ? vx : 0.2f * vx) * at0.y;
            vx = xA0.z + xr0.z + ewA * We0.z; pa += (vx > 0.f ? vx : 0.2f * vx) * at0.z;
            vx = xA0.w + xr0.w + ewA * We0.w; pa += (vx > 0.f ? vx : 0.2f * vx) * at0.w;
            vx = xA1.x + xr1.x + ewA * We1.x; pa += (vx > 0.f ? vx : 0.2f * vx) * at1.x;
            vx = xA1.y + xr1.y + ewA * We1.y; pa += (vx > 0.f ? vx : 0.2f * vx) * at1.y;
            vx = xA1.z + xr1.z + ewA * We1.z; pa += (vx > 0.f ? vx : 0.2f * vx) * at1.z;
            vx = xA1.w + xr1.w + ewA * We1.w; pa += (vx > 0.f ? vx : 0.2f * vx) * at1.w;
            vx = xB0.x + xr0.x + ewB * We0.x; pb += (vx > 0.f ? vx : 0.2f * vx) * at0.x;
            vx = xB0.y + xr0.y + ewB * We0.y; pb += (vx > 0.f ? vx : 0.2f * vx) * at0.y;
            vx = xB0.z + xr0.z + ewB * We0.z; pb += (vx > 0.f ? vx : 0.2f * vx) * at0.z;
            vx = xB0.w + xr0.w + ewB * We0.w; pb += (vx > 0.f ? vx : 0.2f * vx) * at0.w;
            vx = xB1.x + xr1.x + ewB * We1.x; pb += (vx > 0.f ? vx : 0.2f * vx) * at1.x;
            vx = xB1.y + xr1.y + ewB * We1.y; pb += (vx > 0.f ? vx : 0.2f * vx) * at1.y;
            vx = xB1.z + xr1.z + ewB * We1.z; pb += (vx > 0.f ? vx : 0.2f * vx) * at1.z;
            vx = xB1.w + xr1.w + ewB * We1.w; pb += (vx > 0.f ? vx : 0.2f * vx) * at1.w;
            warp_sum2(pa, pb);
            float mn = fmaxf(m, fmaxf(pa, pb));
            float sc = __expf(m - mn);
            float eA = __expf(pa - mn);
            float eB = __expf(pb - mn);
            den = den * sc + eA + eB;
            a0.x = a0.x * sc + eA * xA0.x + eB * xB0.x;
            a0.y = a0.y * sc + eA * xA0.y + eB * xB0.y;
            a0.z = a0.z * sc + eA * xA0.z + eB * xB0.z;
            a0.w = a0.w * sc + eA * xA0.w + eB * xB0.w;
            a1.x = a1.x * sc + eA * xA1.x + eB * xB1.x;
            a1.y = a1.y * sc + eA * xA1.y + eB * xB1.y;
            a1.z = a1.z * sc + eA * xA1.z + eB * xB1.z;
            a1.w = a1.w * sc + eA * xA1.w + eB * xB1.w;
            m = mn;
        }
        if (p < pend) {
            int tok = etok[p];
            float ew = eew[p];
            const float4 x0 = *(const float4*)(g_embL + (size_t)tok * cD + q0);
            const float4 x1 = *(const float4*)(g_embL + (size_t)tok * cD + q1);
            float vx, par = 0.0f;
            vx = x0.x + xr0.x + ew * We0.x; par += (vx > 0.f ? vx : 0.2f * vx) * at0.x;
            vx = x0.y + xr0.y + ew * We0.y; par += (vx > 0.f ? vx : 0.2f * vx) * at0.y;
            vx = x0.z + xr0.z + ew * We0.z; par += (vx > 0.f ? vx : 0.2f * vx) * at0.z;
            vx = x0.w + xr0.w + ew * We0.w; par += (vx > 0.f ? vx : 0.2f * vx) * at0.w;
            vx = x1.x + xr1.x + ew * We1.x; par += (vx > 0.f ? vx : 0.2f * vx) * at1.x;
            vx = x1.y + xr1.y + ew * We1.y; par += (vx > 0.f ? vx : 0.2f * vx) * at1.y;
            vx = x1.z + xr1.z + ew * We1.z; par += (vx > 0.f ? vx : 0.2f * vx) * at1.z;
            vx = x1.w + xr1.w + ew * We1.w; par += (vx > 0.f ? vx : 0.2f * vx) * at1.w;
            float s = warp_sum(par);
            float mn = fmaxf(m, s);
            float sc = __expf(m - mn);
            float pe = __expf(s - mn);
            den = den * sc + pe;
            a0.x = a0.x * sc + pe * x0.x; a0.y = a0.y * sc + pe * x0.y;
            a0.z = a0.z * sc + pe * x0.z; a0.w = a0.w * sc + pe * x0.w;
            a1.x = a1.x * sc + pe * x1.x; a1.y = a1.y * sc + pe * x1.y;
            a1.z = a1.z * sc + pe * x1.z; a1.w = a1.w * sc + pe * x1.w;
        }
        float inv = 1.0f / (den + 1e-16f);
        pm0.x = fmaxf(pm0.x, a0.x * inv + gb0.x);
        pm0.y = fmaxf(pm0.y, a0.y * inv + gb0.y);
        pm0.z = fmaxf(pm0.z, a0.z * inv + gb0.z);
        pm0.w = fmaxf(pm0.w, a0.w * inv + gb0.w);
        pm1.x = fmaxf(pm1.x, a1.x * inv + gb1.x);
        pm1.y = fmaxf(pm1.y, a1.y * inv + gb1.y);
        pm1.z = fmaxf(pm1.z, a1.z * inv + gb1.z);
        pm1.w = fmaxf(pm1.w, a1.w * inv + gb1.w);
    }
    atomicMaxF(&spool[q0 + 0], pm0.x);
    atomicMaxF(&spool[q0 + 1], pm0.y);
    atomicMaxF(&spool[q0 + 2], pm0.z);
    atomicMaxF(&spool[q0 + 3], pm0.w);
    atomicMaxF(&spool[q1 + 0], pm1.x);
    atomicMaxF(&spool[q1 + 1], pm1.y);
    atomicMaxF(&spool[q1 + 2], pm1.z);
    atomicMaxF(&spool[q1 + 3], pm1.w);
    __syncthreads();
    if (tid < cD) g_pooled[g * cD + tid] = spool[tid];
}

// ------------------------- K7: GRU input gates (Wih streamed once/block) ---
__global__ void __launch_bounds__(256) k_gi(const float* __restrict__ Wihf,
                                            const float* __restrict__ bihf,
                                            const float* __restrict__ Wihb,
                                            const float* __restrict__ bihb) {
    const int rg = blockIdx.x, dir = blockIdx.y, tid = threadIdx.x;
    const float* __restrict__ Wih = dir ? Wihb : Wihf;
    const float* __restrict__ bih = dir ? bihb : bihf;
    __shared__ float xs[8][cD];
    for (int i = tid; i < 8 * cD; i += 256) {
        int r = i >> 8, k = i & 255;
        int rr = rg * 8 + r;
        int t = rr / cB, b = rr % cB;
        xs[r][k] = g_pooled[(b * cT + t) * cD + k];
    }
    __syncthreads();
    #pragma unroll
    for (int q = 0; q < 3; q++) {
        int j = q * 256 + tid;
        float acc[8];
        float bj = bih[j];
        #pragma unroll
        for (int r = 0; r < 8; r++) acc[r] = bj;
        const float4* wr = (const float4*)(Wih + (size_t)j * cD);
        #pragma unroll 8
        for (int k4 = 0; k4 < 64; k4++) {
            float4 wv = wr[k4];
            #pragma unroll
            for (int r = 0; r < 8; r++) {
                float4 xx = *(const float4*)&xs[r][k4 * 4];
                acc[r] += wv.x * xx.x + wv.y * xx.y + wv.z * xx.z + wv.w * xx.w;
            }
        }
        #pragma unroll
        for (int r = 0; r < 8; r++)
            g_gi[dir][(size_t)(rg * 8 + r) * 768 + j] = acc[r];
    }
}

// ------------------------- K8: fused GRU (all 8 steps, 1 launch) ----------
__global__ void __launch_bounds__(256) k_gru(const float* __restrict__ Whhf,
                                             const float* __restrict__ bhhf,
                                             const float* __restrict__ Whhb,
                                             const float* __restrict__ bhhb) {
    const int dir = blockIdx.y;
    const int tid = threadIdx.x;
    const int b = tid & 15;
    const int jt = tid >> 4;
    const int i = blockIdx.x * 16 + jt;

    const float* __restrict__ Whh = dir ? Whhb : Whhf;
    const float* __restrict__ bhh = dir ? bhhb : bhhf;
    const float bh0 = bhh[i], bh1 = bhh[i + 256], bh2 = bhh[i + 512];
    const float4* w0 = (const float4*)(Whh + (size_t)i * cD);
    const float4* w1 = (const float4*)(Whh + (size_t)(i + 256) * cD);
    const float4* w2 = (const float4*)(Whh + (size_t)(i + 512) * cD);

    __shared__ float h[cB * cH];

    for (int step = 0; step < cT; step++) {
        const int t = (dir == 0) ? step : (cT - 1 - step);
        const int pin = step & 1, pout = (step + 1) & 1;
        for (int idx = tid; idx < cB * cH; idx += 256)
            h[idx] = g_h[dir][pin][idx];
        __syncthreads();

        const float4* hv = (const float4*)(h + b * cH);
        float hr = 0.0f, hz = 0.0f, hn = 0.0f;
        #pragma unroll 4
        for (int k4 = 0; k4 < 64; k4++) {
            float4 hh = hv[k4];
            float4 a = w0[k4], c = w1[k4], d = w2[k4];
            hr += a.x * hh.x + a.y * hh.y + a.z * hh.z + a.w * hh.w;
            hz += c.x * hh.x + c.y * hh.y + c.z * hh.z + c.w * hh.w;
            hn += d.x * hh.x + d.y * hh.y + d.z * hh.z + d.w * hh.w;
        }
        hr += bh0; hz += bh1; hn += bh2;

        const float* gi = &g_gi[dir][(size_t)(t * cB + b) * 768];
        float r = sigmoidf_(gi[i] + hr);
        float z = sigmoidf_(gi[i + 256] + hz);
        float n = tanhf(gi[i + 512] + r * hn);
        float hp = h[b * cH + i];
        float hnew = (1.0f - z) * n + z * hp;

        g_ys[dir][(size_t)(t * cB + b) * cH + i] = hnew;
        g_h[dir][pout][b * cH + i] = hnew;
        __syncthreads();

        if (step < cT - 1) {
            if (tid == 0) {
                __threadfence();
                unsigned tk = atomicAdd(&g_grubar[dir], 1u);
                unsigned target = (tk / 16u + 1u) * 16u;
                while (atomicAdd(&g_grubar[dir], 0u) < target) {}
                __threadfence();
            }
            __syncthreads();
        }
    }
}

// ------------------------- K9: finalize output -------------------------
__global__ void __launch_bounds__(256) k_fin(float* __restrict__ out) {
    int idx = blockIdx.x * 256 + threadIdx.x;
    const int n1 = cT * cB * cH;
    const int n2 = n1 + cB * cH;
    if (idx < n1) {
        out[idx] = g_ys[0][idx] + g_ys[1][idx];
    } else if (idx < n2) {
        out[idx] = g_ys[0][(cT - 1) * cB * cH + (idx - n1)];
    } else {
        out[idx] = g_ys[1][idx - n2];
    }
}

// ------------------------- launch -------------------------
extern "C" void kernel_launch(void* const* d_in, const int* in_sizes, int n_in,
                              void* d_out, int out_size) {
    const int*   token_ids = (const int*)d_in[0];
    const int*   edge_index = (const int*)d_in[1];
    const float* emb  = (const float*)d_in[2];
    const float* Wl   = (const float*)d_in[3];
    const float* bl   = (const float*)d_in[4];
    const float* Wr   = (const float*)d_in[5];
    const float* br   = (const float*)d_in[6];
    const float* We   = (const float*)d_in[7];
    const float* att  = (const float*)d_in[8];
    const float* gbias = (const float*)d_in[9];
    const float* Wihf = (const float*)d_in[10];
    const float* Whhf = (const float*)d_in[11];
    const float* bihf = (const float*)d_in[12];
    const float* bhhf = (const float*)d_in[13];
    const float* Wihb = (const float*)d_in[14];
    const float* Whhb = (const float*)d_in[15];
    const float* bihb = (const float*)d_in[16];
    const float* bhhb = (const float*)d_in[17];
    float* out = (float*)d_out;

    static cudaStream_t s2 = nullptr;
    static cudaEvent_t evF = nullptr, evS = nullptr, evJ = nullptr;
    if (s2 == nullptr) {
        cudaStreamCreateWithFlags(&s2, cudaStreamNonBlocking);
        cudaEventCreateWithFlags(&evF, cudaEventDisableTiming);
        cudaEventCreateWithFlags(&evS, cudaEventDisableTiming);
        cudaEventCreateWithFlags(&evJ, cudaEventDisableTiming);
    }
    cudaFuncSetAttribute(k_gemm3,
                         cudaFuncAttributeMaxDynamicSharedMemorySize, SMEM3);

    k_tok<<<cG, cL>>>(token_ids);                                     // #1
    cudaEventRecord(evF, 0);
    k_scan<<<1, 512>>>();                                             // #2
    cudaEventRecord(evS, 0);
    k_remap<<<(cV + 255) / 256, 256>>>();                             // #3
    k_splitA<<<(int)(((size_t)cVp * cD) / (256 * 8)), 256>>>(emb);    // #4
    k_splitB<<<dim3(cD, 2), cD>>>(Wl, Wr);                            // #5
    k_gemm3<<<dim3(4, cVp / 128), 256, SMEM3>>>(bl, br);              // #6
    // side stream: w + beta (need tok), ctok (needs scan)
    cudaStreamWaitEvent(s2, evF, 0);
    k_w<<<cG * cE / 16, 256, 0, s2>>>(edge_index, emb);               // #7
    k_beta<<<cG, 256, 0, s2>>>();                                     // #8
    cudaStreamWaitEvent(s2, evS, 0);
    k_ctok<<<cG * cL / 256, 256, 0, s2>>>();                          // #9
    cudaEventRecord(evJ, s2);

    k_zero<<<64, 256>>>();                                            // #10
    cudaStreamWaitEvent(0, evJ, 0);
    k_gat<<<cG, 512>>>(edge_index, We, att, gbias);                   // #11
    k_gi<<<dim3(16, 2), 256>>>(Wihf, bihf, Wihb, bihb);               // #12
    k_gru<<<dim3(16, 2), 256>>>(Whhf, bhhf, Whhb, bhhb);              // #13
    k_fin<<<160, 256>>>(out);                                         // #14
}

// round 13
// speedup vs baseline: 1.2018x; 1.1096x over previous
#include <cuda_runtime.h>
#include <cuda_bf16.h>
#include <cstdint>
#include <math.h>

// Problem constants (fixed by the dataset)
constexpr int cV = 50000;   // vocab
constexpr int cVp = 50048;  // vocab padded to 391*128
constexpr int cD = 256;     // embedding dim
constexpr int cH = 256;     // GRU hidden
constexpr int cB = 16;      // batch
constexpr int cT = 8;       // num_subtrees (time steps)
constexpr int cL = 512;     // subtree_len (nodes per graph)
constexpr int cE = 2048;    // edges per graph
constexpr int cG = cB * cT; // graphs = 128
constexpr int cNW = cVp / 32;  // 1564 bitmap words

// ------------------------- device scratch -------------------------
__device__ float g_embL[(size_t)cVp * cD];  // compact rows: emb@Wl + bl
__device__ float g_embR[(size_t)cVp * cD];
__device__ __nv_bfloat16 g_Ahi[(size_t)cVp * cD];
__device__ __nv_bfloat16 g_Alo[(size_t)cVp * cD];
__device__ __nv_bfloat16 g_Bhi[2][cD * cD];  // W^T split hi: [z][n][k]
__device__ __nv_bfloat16 g_Blo[2][cD * cD];
__device__ int   g_tok[cG * cL];            // original token ids
__device__ int   g_ctok[cG * cL];           // compact token ids
__device__ unsigned g_used[cNW];            // vocab bitmap (idempotent)
__device__ unsigned g_wb[cNW];              // exclusive rank base per word
__device__ int   g_NU;                      // number of used tokens
__device__ int   g_origrow[cVp];            // compact id -> vocab id
__device__ float g_w[cG * cE];
__device__ float g_beta[cG];
__device__ float g_pooled[cG * cD];
__device__ float g_gi[2][cT * cB * 3 * cH];
__device__ float g_h[2][2][cB * cH];        // [dir][parity][b*H]
__device__ float g_ys[2][cT * cB * cH];
__device__ unsigned g_grubar[2];            // GRU inter-CTA barrier tickets

// ------------------------- small utils -------------------------
__device__ __forceinline__ float warp_sum(float v) {
    #pragma unroll
    for (int o = 16; o > 0; o >>= 1) v += __shfl_xor_sync(0xffffffffu, v, o);
    return v;
}
__device__ __forceinline__ void warp_sum2(float& v0, float& v1) {
    #pragma unroll
    for (int o = 16; o > 0; o >>= 1) {
        v0 += __shfl_xor_sync(0xffffffffu, v0, o);
        v1 += __shfl_xor_sync(0xffffffffu, v1, o);
    }
}
__device__ __forceinline__ void warp_sum4(float& v0, float& v1, float& v2,
                                          float& v3) {
    #pragma unroll
    for (int o = 16; o > 0; o >>= 1) {
        v0 += __shfl_xor_sync(0xffffffffu, v0, o);
        v1 += __shfl_xor_sync(0xffffffffu, v1, o);
        v2 += __shfl_xor_sync(0xffffffffu, v2, o);
        v3 += __shfl_xor_sync(0xffffffffu, v3, o);
    }
}
__device__ __forceinline__ void atomicMaxF(float* addr, float val) {
    int* ia = (int*)addr;
    int old = __float_as_int(*addr);
    while (__int_as_float(old) < val) {
        int prev = atomicCAS(ia, old, __float_as_int(val));
        if (prev == old) break;
        old = prev;
    }
}
__device__ __forceinline__ float sigmoidf_(float x) { return 1.0f / (1.0f + expf(-x)); }
__device__ __forceinline__ int tok_rank(int tok) {
    int word = tok >> 5, bit = tok & 31;
    return (int)g_wb[word] + __popc(g_used[word] & ((1u << bit) - 1u));
}

// ------------------------- mma.sync helpers -------------------------
__device__ __forceinline__ uint32_t smem_u32(const void* p) {
    uint32_t a;
    asm("{ .reg .u64 t; cvta.to.shared.u64 t, %1; cvt.u32.u64 %0, t; }"
        : "=r"(a) : "l"(p));
    return a;
}
__device__ __forceinline__ void ldm_x4(uint32_t& r0, uint32_t& r1, uint32_t& r2,
                                       uint32_t& r3, uint32_t addr) {
    asm volatile("ldmatrix.sync.aligned.m8n8.x4.shared.b16 {%0,%1,%2,%3}, [%4];"
                 : "=r"(r0), "=r"(r1), "=r"(r2), "=r"(r3) : "r"(addr));
}
__device__ __forceinline__ void mma16816(float* d, uint32_t a0, uint32_t a1,
                                         uint32_t a2, uint32_t a3,
                                         uint32_t b0, uint32_t b1) {
    asm volatile(
        "mma.sync.aligned.m16n8k16.row.col.f32.bf16.bf16.f32 "
        "{%0,%1,%2,%3}, {%4,%5,%6,%7}, {%8,%9}, {%0,%1,%2,%3};"
        : "+f"(d[0]), "+f"(d[1]), "+f"(d[2]), "+f"(d[3])
        : "r"(a0), "r"(a1), "r"(a2), "r"(a3), "r"(b0), "r"(b1));
}
__device__ __forceinline__ void cpa16(uint32_t dst, const void* src) {
    asm volatile("cp.async.cg.shared.global [%0], [%1], 16;" :: "r"(dst),
                 "l"(src));
}
__device__ __forceinline__ void cpa_commit() {
    asm volatile("cp.async.commit_group;" ::: "memory");
}
__device__ __forceinline__ void cpa_wait0() {
    asm volatile("cp.async.wait_group 0;" ::: "memory");
}

// ------------------------- K0: token LUT + used bitmap -------------------------
__global__ void k_tok(const int* __restrict__ token_ids) {
    int g = blockIdx.x, l = threadIdx.x;
    int b = g / cT, t = g % cT;
    int tok = token_ids[(t * cL + l) * cB + b];
    g_tok[g * cL + l] = tok;
    atomicOr(&g_used[tok >> 5], 1u << (tok & 31));  // idempotent across replays
}

// scan bitmap popcounts -> per-word exclusive base + total count
__global__ void __launch_bounds__(512) k_scan() {
    __shared__ unsigned ts[512];
    const int tid = threadIdx.x;
    unsigned loc[4];
    unsigned s = 0;
    #pragma unroll
    for (int i = 0; i < 4; i++) {
        int w = tid * 4 + i;
        loc[i] = s;
        if (w < cNW) s += (unsigned)__popc(g_used[w]);
    }
    ts[tid] = s;
    __syncthreads();
    for (int off = 1; off < 512; off <<= 1) {
        unsigned v = (tid >= off) ? ts[tid - off] : 0u;
        __syncthreads();
        ts[tid] += v;
        __syncthreads();
    }
    unsigned base = tid ? ts[tid - 1] : 0u;
    #pragma unroll
    for (int i = 0; i < 4; i++) {
        int w = tid * 4 + i;
        if (w < cNW) g_wb[w] = base + loc[i];
    }
    if (tid == 511) g_NU = (int)ts[511];
}

// compact id -> vocab id
__global__ void __launch_bounds__(256) k_remap() {
    int v = blockIdx.x * 256 + threadIdx.x;
    if (v >= cV) return;
    unsigned bits = g_used[v >> 5];
    int bit = v & 31;
    if ((bits >> bit) & 1u) {
        int rank = (int)g_wb[v >> 5] + __popc(bits & ((1u << bit) - 1u));
        g_origrow[rank] = v;
    }
}

// per-node compact token
__global__ void __launch_bounds__(256) k_ctok() {
    int i = blockIdx.x * 256 + threadIdx.x;
    g_ctok[i] = tok_rank(g_tok[i]);
}

__global__ void k_zero() {
    int idx = blockIdx.x * 256 + threadIdx.x;
    ((float*)g_h)[idx] = 0.0f;
}

// ------------------------- split-precision conversion (gathered) ----------
__global__ void __launch_bounds__(256) k_splitA(const float* __restrict__ emb) {
    size_t idx = ((size_t)blockIdx.x * 256 + threadIdx.x) * 8;
    int row = (int)(idx >> 8);
    int col = (int)(idx & 255);
    int nu = g_NU;
    float v[8];
    if (row < nu) {
        size_t src = (size_t)g_origrow[row] * cD + col;
        float4 a = *(const float4*)(emb + src);
        float4 b = *(const float4*)(emb + src + 4);
        v[0] = a.x; v[1] = a.y; v[2] = a.z; v[3] = a.w;
        v[4] = b.x; v[5] = b.y; v[6] = b.z; v[7] = b.w;
    } else {
        #pragma unroll
        for (int i = 0; i < 8; i++) v[i] = 0.0f;
    }
    __nv_bfloat16 hi[8], lo[8];
    #pragma unroll
    for (int i = 0; i < 8; i++) {
        hi[i] = __float2bfloat16_rn(v[i]);
        lo[i] = __float2bfloat16_rn(v[i] - __bfloat162float(hi[i]));
    }
    *(uint4*)(g_Ahi + idx) = *(uint4*)hi;
    *(uint4*)(g_Alo + idx) = *(uint4*)lo;
}

// W -> W^T hi/lo bf16 (B operand is [n][k], K-contiguous)
__global__ void __launch_bounds__(256) k_splitB(const float* __restrict__ Wl,
                                                const float* __restrict__ Wr) {
    int z = blockIdx.y, n = blockIdx.x, k = threadIdx.x;
    const float* W = z ? Wr : Wl;
    float x = W[(size_t)k * cD + n];
    __nv_bfloat16 hi = __float2bfloat16_rn(x);
    __nv_bfloat16 lo = __float2bfloat16_rn(x - __bfloat162float(hi));
    g_Bhi[z][n * cD + k] = hi;
    g_Blo[z][n * cD + k] = lo;
}

// ------------------------- K1: mma.sync bf16 split GEMM (R9 config) -------
constexpr int SST = 72;                       // halves per smem row (144B)
constexpr int TILE3 = 128 * SST;              // halves per tile
constexpr int SMEM3 = 4 * TILE3 * 2;          // 73728 B

__global__ void __launch_bounds__(256, 2)
k_gemm3(const float* __restrict__ bl, const float* __restrict__ br) {
    const int m0 = blockIdx.y * 128;
    if (m0 >= g_NU) return;                   // compacted: nothing to do

    extern __shared__ __nv_bfloat16 sm3[];
    const uint32_t sb = smem_u32(sm3);
    const uint32_t uAh = sb;
    const uint32_t uAl = sb + TILE3 * 2;
    const uint32_t uBh = sb + 2 * TILE3 * 2;
    const uint32_t uBl = sb + 3 * TILE3 * 2;

    const int tid = threadIdx.x, wid = tid >> 5, lane = tid & 31;
    const int nhalf = blockIdx.x & 1, z = blockIdx.x >> 1;
    const int n0 = nhalf * 128;
    const __nv_bfloat16* __restrict__ gBh = g_Bhi[z];
    const __nv_bfloat16* __restrict__ gBl = g_Blo[z];

    const int mw = (wid & 1) * 64;
    const int nw = (wid >> 1) * 32;
    const int aRow = mw + (lane & 15);
    const int aK = (lane >> 4) * 8;
    const int bN = ((lane >> 4) & 1) * 8 + (lane & 7);
    const int bK = ((lane >> 3) & 1) * 8;

    float acc[4][4][4];
    #pragma unroll
    for (int mi = 0; mi < 4; mi++)
        #pragma unroll
        for (int ni = 0; ni < 4; ni++)
            #pragma unroll
            for (int q = 0; q < 4; q++) acc[mi][ni][q] = 0.0f;

    for (int kb = 0; kb < 256; kb += 64) {
        #pragma unroll
        for (int i = 0; i < 4; i++) {
            int idx = tid + i * 256;
            int r = idx >> 3, s = idx & 7;
            size_t gs = (size_t)(m0 + r) * cD + kb + s * 8;
            uint32_t d = (uint32_t)((r * SST + s * 8) * 2);
            cpa16(uAh + d, g_Ahi + gs);
            cpa16(uAl + d, g_Alo + gs);
        }
        #pragma unroll
        for (int i = 0; i < 4; i++) {
            int idx = tid + i * 256;
            int r = idx >> 3, s = idx & 7;
            size_t gs = (size_t)(n0 + r) * cD + kb + s * 8;
            uint32_t d = (uint32_t)((r * SST + s * 8) * 2);
            cpa16(uBh + d, gBh + gs);
            cpa16(uBl + d, gBl + gs);
        }
        cpa_commit();
        cpa_wait0();
        __syncthreads();

        #pragma unroll
        for (int ks = 0; ks < 4; ks++) {
            const int kk = ks * 16;
            uint32_t ah[4][4], al[4][4], bh[4][2], bl2[4][2];
            #pragma unroll
            for (int mi = 0; mi < 4; mi++) {
                uint32_t off =
                    (uint32_t)(((aRow + mi * 16) * SST + kk + aK) * 2);
                ldm_x4(ah[mi][0], ah[mi][1], ah[mi][2], ah[mi][3], uAh + off);
                ldm_x4(al[mi][0], al[mi][1], al[mi][2], al[mi][3], uAl + off);
            }
            #pragma unroll
            for (int nj = 0; nj < 2; nj++) {
                uint32_t off =
                    (uint32_t)(((nw + nj * 16 + bN) * SST + kk + bK) * 2);
                ldm_x4(bh[2 * nj][0], bh[2 * nj][1], bh[2 * nj + 1][0],
                       bh[2 * nj + 1][1], uBh + off);
                ldm_x4(bl2[2 * nj][0], bl2[2 * nj][1], bl2[2 * nj + 1][0],
                       bl2[2 * nj + 1][1], uBl + off);
            }
            #pragma unroll
            for (int mi = 0; mi < 4; mi++)
                #pragma unroll
                for (int ni = 0; ni < 4; ni++) {
                    mma16816(acc[mi][ni], ah[mi][0], ah[mi][1], ah[mi][2],
                             ah[mi][3], bh[ni][0], bh[ni][1]);
                    mma16816(acc[mi][ni], ah[mi][0], ah[mi][1], ah[mi][2],
                             ah[mi][3], bl2[ni][0], bl2[ni][1]);
                    mma16816(acc[mi][ni], al[mi][0], al[mi][1], al[mi][2],
                             al[mi][3], bh[ni][0], bh[ni][1]);
                }
        }
        __syncthreads();
    }

    const float* __restrict__ bias = z ? br : bl;
    float* __restrict__ out = z ? g_embR : g_embL;
    const int mbase = m0 + mw + (lane >> 2);
    #pragma unroll
    for (int ni = 0; ni < 4; ni++) {
        int col = n0 + nw + ni * 8 + (lane & 3) * 2;
        float2 bv = *(const float2*)(bias + col);
        #pragma unroll
        for (int mi = 0; mi < 4; mi++) {
            int mg0 = mbase + mi * 16;
            int mg1 = mg0 + 8;
            float2 o0 = make_float2(acc[mi][ni][0] + bv.x,
                                    acc[mi][ni][1] + bv.y);
            *(float2*)(out + (size_t)mg0 * cD + col) = o0;
            float2 o1 = make_float2(acc[mi][ni][2] + bv.x,
                                    acc[mi][ni][3] + bv.y);
            *(float2*)(out + (size_t)mg1 * cD + col) = o1;
        }
    }
}

// ------------------------- K2: edge pass 1 (w), 2 edges/warp -------------------------
__global__ void __launch_bounds__(256) k_w(const int* __restrict__ eidx,
                                           const float* __restrict__ emb) {
    int wrp = blockIdx.x * 8 + (threadIdx.x >> 5);
    int lane = threadIdx.x & 31;
    int gw0 = wrp * 2;
    int g = gw0 / cE;
    int e0 = gw0 % cE;
    const int* __restrict__ srcb = eidx + (size_t)(g * 2) * cE;
    const int* __restrict__ dstb = srcb + cE;
    int s0 = srcb[e0], s1 = srcb[e0 + 1];
    int d0 = dstb[e0], d1 = dstb[e0 + 1];
    int ts0 = g_tok[g * cL + s0], ts1 = g_tok[g * cL + s1];
    int td0 = g_tok[g * cL + d0], td1 = g_tok[g * cL + d1];
    const float4* a0p = (const float4*)(emb + (size_t)ts0 * cD);
    const float4* b0p = (const float4*)(emb + (size_t)td0 * cD);
    const float4* a1p = (const float4*)(emb + (size_t)ts1 * cD);
    const float4* b1p = (const float4*)(emb + (size_t)td1 * cD);
    float ss0 = 0.0f, ss1 = 0.0f;
    #pragma unroll
    for (int i = 0; i < 2; i++) {
        int j = lane + i * 32;
        float4 a0 = a0p[j], b0 = b0p[j], a1 = a1p[j], b1 = b1p[j];
        float x0 = a0.x - b0.x, y0 = a0.y - b0.y, z0 = a0.z - b0.z,
              w0 = a0.w - b0.w;
        float x1 = a1.x - b1.x, y1 = a1.y - b1.y, z1 = a1.z - b1.z,
              w1 = a1.w - b1.w;
        ss0 += x0 * x0 + y0 * y0 + z0 * z0 + w0 * w0;
        ss1 += x1 * x1 + y1 * y1 + z1 * z1 + w1 * w1;
    }
    warp_sum2(ss0, ss1);
    if (lane == 0) {
        g_w[gw0] = sqrtf(ss0 + 1e-12f);
        g_w[gw0 + 1] = sqrtf(ss1 + 1e-12f);
    }
}

// ------------------------- K3: beta -------------------------
__global__ void __launch_bounds__(256) k_beta() {
    int g = blockIdx.x, tid = threadIdx.x;
    __shared__ float sm[256];
    float s = 0.0f;
    for (int e = tid; e < cE; e += 256) s += g_w[g * cE + e];
    sm[tid] = s;
    __syncthreads();
    for (int o = 128; o > 0; o >>= 1) {
        if (tid < o) sm[tid] += sm[tid + o];
        __syncthreads();
    }
    if (tid == 0) g_beta[g] = sm[0] / (float)cE;
}

// ------------------------- K4: fused GAT (score+softmax+agg+pool) ----------
__device__ __forceinline__ float edge_score(const float4& x0, const float4& x1,
                                            const float4& xr0, const float4& xr1,
                                            float ew, const float4& We0,
                                            const float4& We1, const float4& at0,
                                            const float4& at1) {
    float vx, p = 0.0f;
    vx = x0.x + xr0.x + ew * We0.x; p += (vx > 0.f ? vx : 0.2f * vx) * at0.x;
    vx = x0.y + xr0.y + ew * We0.y; p += (vx > 0.f ? vx : 0.2f * vx) * at0.y;
    vx = x0.z + xr0.z + ew * We0.z; p += (vx > 0.f ? vx : 0.2f * vx) * at0.z;
    vx = x0.w + xr0.w + ew * We0.w; p += (vx > 0.f ? vx : 0.2f * vx) * at0.w;
    vx = x1.x + xr1.x + ew * We1.x; p += (vx > 0.f ? vx : 0.2f * vx) * at1.x;
    vx = x1.y + xr1.y + ew * We1.y; p += (vx > 0.f ? vx : 0.2f * vx) * at1.y;
    vx = x1.z + xr1.z + ew * We1.z; p += (vx > 0.f ? vx : 0.2f * vx) * at1.z;
    vx = x1.w + xr1.w + ew * We1.w; p += (vx > 0.f ? vx : 0.2f * vx) * at1.w;
    return p;
}

__global__ void __launch_bounds__(512) k_gat(const int* __restrict__ eidx,
                                             const float* __restrict__ We,
                                             const float* __restrict__ att,
                                             const float* __restrict__ gbias) {
    const int g = blockIdx.x;
    const int tid = threadIdx.x, lane = tid & 31, wrp = tid >> 5;
    __shared__ int off[cL + 1];
    __shared__ int cnt[cL];
    __shared__ int etok[cE];
    __shared__ float eew[cE];
    __shared__ float spool[cD];

    for (int i = tid; i < cL; i += 512) cnt[i] = 0;
    if (tid < cD) spool[tid] = -1e30f;
    __syncthreads();
    for (int e = tid; e < cE; e += 512) {
        int d = eidx[(size_t)(g * 2 + 1) * cE + e];
        atomicAdd(&cnt[d], 1);
    }
    __syncthreads();
    if (tid == 0) off[0] = 0;
    off[tid + 1] = cnt[tid];
    __syncthreads();
    #pragma unroll
    for (int st = 1; st < cL; st <<= 1) {
        int v = off[tid + 1];
        if (tid >= st) v += off[tid + 1 - st];
        __syncthreads();
        off[tid + 1] = v;
        __syncthreads();
    }
    cnt[tid] = 0;
    __syncthreads();
    {
        float beta = g_beta[g];
        float c = -0.5f / (beta * beta);
        for (int e = tid; e < cE; e += 512) {
            int d = eidx[(size_t)(g * 2 + 1) * cE + e];
            int s = eidx[(size_t)(g * 2) * cE + e];
            int pos = off[d] + atomicAdd(&cnt[d], 1);
            etok[pos] = g_ctok[g * cL + s];
            float w = g_w[g * cE + e];
            eew[pos] = __expf(w * w * c);
        }
    }
    __syncthreads();

    const int q0 = lane * 4, q1 = 128 + lane * 4;
    const float4 We0 = *(const float4*)(We + q0);
    const float4 We1 = *(const float4*)(We + q1);
    const float4 at0 = *(const float4*)(att + q0);
    const float4 at1 = *(const float4*)(att + q1);
    const float4 gb0 = *(const float4*)(gbias + q0);
    const float4 gb1 = *(const float4*)(gbias + q1);
    float4 pm0 = make_float4(-1e30f, -1e30f, -1e30f, -1e30f);
    float4 pm1 = pm0;

    for (int dst = wrp; dst < cL; dst += 16) {
        int tokd = g_ctok[g * cL + dst];
        const float4 xr0 = *(const float4*)(g_embR + (size_t)tokd * cD + q0);
        const float4 xr1 = *(const float4*)(g_embR + (size_t)tokd * cD + q1);
        float m = -1e30f, den = 0.0f;
        float4 a0 = make_float4(0.f, 0.f, 0.f, 0.f), a1 = a0;
        const int pend = off[dst + 1];
        int p = off[dst];
        // ---- 4 edges per iteration ----
        for (; p + 3 < pend; p += 4) {
            int tA = etok[p], tB = etok[p + 1], tC = etok[p + 2],
                tD = etok[p + 3];
            float ewA = eew[p], ewB = eew[p + 1], ewC = eew[p + 2],
                  ewD = eew[p + 3];
            const float4 xA0 = *(const float4*)(g_embL + (size_t)tA * cD + q0);
            const float4 xA1 = *(const float4*)(g_embL + (size_t)tA * cD + q1);
            const float4 xB0 = *(const float4*)(g_embL + (size_t)tB * cD + q0);
            const float4 xB1 = *(const float4*)(g_embL + (size_t)tB * cD + q1);
            const float4 xC0 = *(const float4*)(g_embL + (size_t)tC * cD + q0);
            const float4 xC1 = *(const float4*)(g_embL + (size_t)tC * cD + q1);
            const float4 xD0 = *(const float4*)(g_embL + (size_t)tD * cD + q0);
            const float4 xD1 = *(const float4*)(g_embL + (size_t)tD * cD + q1);
            float pa = edge_score(xA0, xA1, xr0, xr1, ewA, We0, We1, at0, at1);
            float pb = edge_score(xB0, xB1, xr0, xr1, ewB, We0, We1, at0, at1);
            float pc = edge_score(xC0, xC1, xr0, xr1, ewC, We0, We1, at0, at1);
            float pd = edge_score(xD0, xD1, xr0, xr1, ewD, We0, We1, at0, at1);
            warp_sum4(pa, pb, pc, pd);
            float mn = fmaxf(fmaxf(m, fmaxf(pa, pb)), fmaxf(pc, pd));
            float sc = __expf(m - mn);
            float eA = __expf(pa - mn);
            float eB = __expf(pb - mn);
            float eC = __expf(pc - mn);
            float eD = __expf(pd - mn);
            den = den * sc + eA + eB + eC + eD;
            a0.x = a0.x * sc + eA * xA0.x + eB * xB0.x + eC * xC0.x + eD * xD0.x;
            a0.y = a0.y * sc + eA * xA0.y + eB * xB0.y + eC * xC0.y + eD * xD0.y;
            a0.z = a0.z * sc + eA * xA0.z + eB * xB0.z + eC * xC0.z + eD * xD0.z;
            a0.w = a0.w * sc + eA * xA0.w + eB * xB0.w + eC * xC0.w + eD * xD0.w;
            a1.x = a1.x * sc + eA * xA1.x + eB * xB1.x + eC * xC1.x + eD * xD1.x;
            a1.y = a1.y * sc + eA * xA1.y + eB * xB1.y + eC * xC1.y + eD * xD1.y;
            a1.z = a1.z * sc + eA * xA1.z + eB * xB1.z + eC * xC1.z + eD * xD1.z;
            a1.w = a1.w * sc + eA * xA1.w + eB * xB1.w + eC * xC1.w + eD * xD1.w;
            m = mn;
        }
        // ---- 2-edge block ----
        if (p + 1 < pend) {
            int tA = etok[p], tB = etok[p + 1];
            float ewA = eew[p], ewB = eew[p + 1];
            const float4 xA0 = *(const float4*)(g_embL + (size_t)tA * cD + q0);
            const float4 xA1 = *(const float4*)(g_embL + (size_t)tA * cD + q1);
            const float4 xB0 = *(const float4*)(g_embL + (size_t)tB * cD + q0);
            const float4 xB1 = *(const float4*)(g_embL + (size_t)tB * cD + q1);
            float pa = edge_score(xA0, xA1, xr0, xr1, ewA, We0, We1, at0, at1);
            float pb = edge_score(xB0, xB1, xr0, xr1, ewB, We0, We1, at0, at1);
            warp_sum2(pa, pb);
            float mn = fmaxf(m, fmaxf(pa, pb));
            float sc = __expf(m - mn);
            float eA = __expf(pa - mn);
            float eB = __expf(pb - mn);
            den = den * sc + eA + eB;
            a0.x = a0.x * sc + eA * xA0.x + eB * xB0.x;
            a0.y = a0.y * sc + eA * xA0.y + eB * xB0.y;
            a0.z = a0.z * sc + eA * xA0.z + eB * xB0.z;
            a0.w = a0.w * sc + eA * xA0.w + eB * xB0.w;
            a1.x = a1.x * sc + eA * xA1.x + eB * xB1.x;
            a1.y = a1.y * sc + eA * xA1.y + eB * xB1.y;
            a1.z = a1.z * sc + eA * xA1.z + eB * xB1.z;
            a1.w = a1.w * sc + eA * xA1.w + eB * xB1.w;
            m = mn;
            p += 2;
        }
        // ---- single tail ----
        if (p < pend) {
            int tok = etok[p];
            float ew = eew[p];
            const float4 x0 = *(const float4*)(g_embL + (size_t)tok * cD + q0);
            const float4 x1 = *(const float4*)(g_embL + (size_t)tok * cD + q1);
            float par = edge_score(x0, x1, xr0, xr1, ew, We0, We1, at0, at1);
            float s = warp_sum(par);
            float mn = fmaxf(m, s);
            float sc = __expf(m - mn);
            float pe = __expf(s - mn);
            den = den * sc + pe;
            a0.x = a0.x * sc + pe * x0.x; a0.y = a0.y * sc + pe * x0.y;
            a0.z = a0.z * sc + pe * x0.z; a0.w = a0.w * sc + pe * x0.w;
            a1.x = a1.x * sc + pe * x1.x; a1.y = a1.y * sc + pe * x1.y;
            a1.z = a1.z * sc + pe * x1.z; a1.w = a1.w * sc + pe * x1.w;
        }
        float inv = 1.0f / (den + 1e-16f);
        pm0.x = fmaxf(pm0.x, a0.x * inv + gb0.x);
        pm0.y = fmaxf(pm0.y, a0.y * inv + gb0.y);
        pm0.z = fmaxf(pm0.z, a0.z * inv + gb0.z);
        pm0.w = fmaxf(pm0.w, a0.w * inv + gb0.w);
        pm1.x = fmaxf(pm1.x, a1.x * inv + gb1.x);
        pm1.y = fmaxf(pm1.y, a1.y * inv + gb1.y);
        pm1.z = fmaxf(pm1.z, a1.z * inv + gb1.z);
        pm1.w = fmaxf(pm1.w, a1.w * inv + gb1.w);
    }
    atomicMaxF(&spool[q0 + 0], pm0.x);
    atomicMaxF(&spool[q0 + 1], pm0.y);
    atomicMaxF(&spool[q0 + 2], pm0.z);
    atomicMaxF(&spool[q0 + 3], pm0.w);
    atomicMaxF(&spool[q1 + 0], pm1.x);
    atomicMaxF(&spool[q1 + 1], pm1.y);
    atomicMaxF(&spool[q1 + 2], pm1.z);
    atomicMaxF(&spool[q1 + 3], pm1.w);
    __syncthreads();
    if (tid < cD) g_pooled[g * cD + tid] = spool[tid];
}

// ------------------------- K7: GRU input gates (Wih streamed once/block) ---
__global__ void __launch_bounds__(256) k_gi(const float* __restrict__ Wihf,
                                            const float* __restrict__ bihf,
                                            const float* __restrict__ Wihb,
                                            const float* __restrict__ bihb) {
    const int rg = blockIdx.x, dir = blockIdx.y, tid = threadIdx.x;
    const float* __restrict__ Wih = dir ? Wihb : Wihf;
    const float* __restrict__ bih = dir ? bihb : bihf;
    __shared__ float xs[8][cD];
    for (int i = tid; i < 8 * cD; i += 256) {
        int r = i >> 8, k = i & 255;
        int rr = rg * 8 + r;
        int t = rr / cB, b = rr % cB;
        xs[r][k] = g_pooled[(b * cT + t) * cD + k];
    }
    __syncthreads();
    #pragma unroll
    for (int q = 0; q < 3; q++) {
        int j = q * 256 + tid;
        float acc[8];
        float bj = bih[j];
        #pragma unroll
        for (int r = 0; r < 8; r++) acc[r] = bj;
        const float4* wr = (const float4*)(Wih + (size_t)j * cD);
        #pragma unroll 8
        for (int k4 = 0; k4 < 64; k4++) {
            float4 wv = wr[k4];
            #pragma unroll
            for (int r = 0; r < 8; r++) {
                float4 xx = *(const float4*)&xs[r][k4 * 4];
                acc[r] += wv.x * xx.x + wv.y * xx.y + wv.z * xx.z + wv.w * xx.w;
            }
        }
        #pragma unroll
        for (int r = 0; r < 8; r++)
            g_gi[dir][(size_t)(rg * 8 + r) * 768 + j] = acc[r];
    }
}

// ------------------------- K8: fused GRU (64 CTAs, all 8 steps) -----------
// grid (32, 2), 128 threads: i = bx*8 + (tid>>4), b = tid&15.
// Ticket barrier per dir counts 32 CTAs (advances in multiples of 32).
__global__ void __launch_bounds__(128) k_gru(const float* __restrict__ Whhf,
                                             const float* __restrict__ bhhf,
                                             const float* __restrict__ Whhb,
                                             const float* __restrict__ bhhb) {
    const int dir = blockIdx.y;
    const int tid = threadIdx.x;
    const int b = tid & 15;
    const int jt = tid >> 4;          // 0..7
    const int i = blockIdx.x * 8 + jt;

    const float* __restrict__ Whh = dir ? Whhb : Whhf;
    const float* __restrict__ bhh = dir ? bhhb : bhhf;
    const float bh0 = bhh[i], bh1 = bhh[i + 256], bh2 = bhh[i + 512];
    const float4* w0 = (const float4*)(Whh + (size_t)i * cD);
    const float4* w1 = (const float4*)(Whh + (size_t)(i + 256) * cD);
    const float4* w2 = (const float4*)(Whh + (size_t)(i + 512) * cD);

    __shared__ float h[cB * cH];

    for (int step = 0; step < cT; step++) {
        const int t = (dir == 0) ? step : (cT - 1 - step);
        const int pin = step & 1, pout = (step + 1) & 1;
        {
            float4* h4 = (float4*)h;
            const float4* g4 = (const float4*)g_h[dir][pin];
            for (int idx = tid; idx < cB * cH / 4; idx += 128) h4[idx] = g4[idx];
        }
        __syncthreads();

        const float4* hv = (const float4*)(h + b * cH);
        float hr = 0.0f, hz = 0.0f, hn = 0.0f;
        #pragma unroll 4
        for (int k4 = 0; k4 < 64; k4++) {
            float4 hh = hv[k4];
            float4 a = w0[k4], c = w1[k4], d = w2[k4];
            hr += a.x * hh.x + a.y * hh.y + a.z * hh.z + a.w * hh.w;
            hz += c.x * hh.x + c.y * hh.y + c.z * hh.z + c.w * hh.w;
            hn += d.x * hh.x + d.y * hh.y + d.z * hh.z + d.w * hh.w;
        }
        hr += bh0; hz += bh1; hn += bh2;

        const float* gi = &g_gi[dir][(size_t)(t * cB + b) * 768];
        float r = sigmoidf_(gi[i] + hr);
        float z = sigmoidf_(gi[i + 256] + hz);
        float n = tanhf(gi[i + 512] + r * hn);
        float hp = h[b * cH + i];
        float hnew = (1.0f - z) * n + z * hp;

        g_ys[dir][(size_t)(t * cB + b) * cH + i] = hnew;
        g_h[dir][pout][b * cH + i] = hnew;
        __syncthreads();

        if (step < cT - 1) {
            if (tid == 0) {
                __threadfence();
                unsigned tk = atomicAdd(&g_grubar[dir], 1u);
                unsigned target = (tk / 32u + 1u) * 32u;
                while (atomicAdd(&g_grubar[dir], 0u) < target) {}
                __threadfence();
            }
            __syncthreads();
        }
    }
}

// ------------------------- K9: finalize output -------------------------
__global__ void __launch_bounds__(256) k_fin(float* __restrict__ out) {
    int idx = blockIdx.x * 256 + threadIdx.x;
    const int n1 = cT * cB * cH;
    const int n2 = n1 + cB * cH;
    if (idx < n1) {
        out[idx] = g_ys[0][idx] + g_ys[1][idx];
    } else if (idx < n2) {
        out[idx] = g_ys[0][(cT - 1) * cB * cH + (idx - n1)];
    } else {
        out[idx] = g_ys[1][idx - n2];
    }
}

// ------------------------- launch -------------------------
extern "C" void kernel_launch(void* const* d_in, const int* in_sizes, int n_in,
                              void* d_out, int out_size) {
    const int*   token_ids = (const int*)d_in[0];
    const int*   edge_index = (const int*)d_in[1];
    const float* emb  = (const float*)d_in[2];
    const float* Wl   = (const float*)d_in[3];
    const float* bl   = (const float*)d_in[4];
    const float* Wr   = (const float*)d_in[5];
    const float* br   = (const float*)d_in[6];
    const float* We   = (const float*)d_in[7];
    const float* att  = (const float*)d_in[8];
    const float* gbias = (const float*)d_in[9];
    const float* Wihf = (const float*)d_in[10];
    const float* Whhf = (const float*)d_in[11];
    const float* bihf = (const float*)d_in[12];
    const float* bhhf = (const float*)d_in[13];
    const float* Wihb = (const float*)d_in[14];
    const float* Whhb = (const float*)d_in[15];
    const float* bihb = (const float*)d_in[16];
    const float* bhhb = (const float*)d_in[17];
    float* out = (float*)d_out;

    static cudaStream_t s2 = nullptr;
    static cudaEvent_t evF = nullptr, evS = nullptr, evJ = nullptr;
    if (s2 == nullptr) {
        cudaStreamCreateWithFlags(&s2, cudaStreamNonBlocking);
        cudaEventCreateWithFlags(&evF, cudaEventDisableTiming);
        cudaEventCreateWithFlags(&evS, cudaEventDisableTiming);
        cudaEventCreateWithFlags(&evJ, cudaEventDisableTiming);
    }
    cudaFuncSetAttribute(k_gemm3,
                         cudaFuncAttributeMaxDynamicSharedMemorySize, SMEM3);

    k_tok<<<cG, cL>>>(token_ids);                                     // #1
    cudaEventRecord(evF, 0);
    k_scan<<<1, 512>>>();                                             // #2
    cudaEventRecord(evS, 0);
    k_remap<<<(cV + 255) / 256, 256>>>();                             // #3
    k_splitA<<<(int)(((size_t)cVp * cD) / (256 * 8)), 256>>>(emb);    // #4
    k_splitB<<<dim3(cD, 2), cD>>>(Wl, Wr);                            // #5
    k_gemm3<<<dim3(4, cVp / 128), 256, SMEM3>>>(bl, br);              // #6
    // side stream: w + beta (need tok), ctok (needs scan)
    cudaStreamWaitEvent(s2, evF, 0);
    k_w<<<cG * cE / 16, 256, 0, s2>>>(edge_index, emb);               // #7
    k_beta<<<cG, 256, 0, s2>>>();                                     // #8
    cudaStreamWaitEvent(s2, evS, 0);
    k_ctok<<<cG * cL / 256, 256, 0, s2>>>();                          // #9
    cudaEventRecord(evJ, s2);

    k_zero<<<64, 256>>>();                                            // #10
    cudaStreamWaitEvent(0, evJ, 0);
    k_gat<<<cG, 512>>>(edge_index, We, att, gbias);                   // #11
    k_gi<<<dim3(16, 2), 256>>>(Wihf, bihf, Wihb, bihb);               // #12
    k_gru<<<dim3(32, 2), 128>>>(Whhf, bhhf, Whhb, bhhb);              // #13
    k_fin<<<160, 256>>>(out);                                         // #14
}